// round 12
// baseline (speedup 1.0000x reference)
#include <cuda_runtime.h>
#include <cuda_bf16.h>
#include <math.h>

#define NPTS 4096
#define BITD 64
#define LLAB 10
#define RT   256
#define UPPERB 16.0f
// c = (1/right)*ln(yp/(99(1-yp))) with right=64/6, yp=0.5  -> -6*ln(99)/64
#define CONST_C    (-0.43079248594386178f)
#define CONST_AC   (-0.86158497188772356f)   // a*c, a = 2 exactly
#define CONST_BASE (0.0f)

#define CANDSZ 512
#define SMALLN 64
#define SCW    134.7368421f    // 256 / 1.9   (window width 1.9 sigma)
#define OFC    323.3684211f    // 2.4 * 256 / 1.9

#define KW   32          // 32 b32 words per row (64 bf16)
#define SPAD 36          // padded row stride in words

// ---------------- device scratch ----------------
__device__ float    g_inner[(size_t)NPTS * NPTS];   // 64 MB
__device__ unsigned g_maskArr[NPTS];
__device__ unsigned g_Ybits[LLAB * (NPTS / 32)];
__device__ float2   g_rowout[NPTS];
__device__ unsigned g_ctr;
__device__ float    g_sigR[NPTS];    // sigma = |u_i|
__device__ float    g_sigI[NPTS];    // 1/sigma (0 if degenerate)

// ---------------- helpers ----------------
__device__ __forceinline__ unsigned fkey(float f) {
    unsigned u = __float_as_uint(f);
    return u ^ (((unsigned)((int)u >> 31)) | 0x80000000u);
}
__device__ __forceinline__ float finv(unsigned k) {
    unsigned u = (k & 0x80000000u) ? (k ^ 0x80000000u) : ~k;
    return __uint_as_float(u);
}

__device__ __forceinline__ float4 blockReduce4(float4 v, float4* sh) {
    int tid = threadIdx.x, lane = tid & 31, wid = tid >> 5;
    #pragma unroll
    for (int o = 16; o > 0; o >>= 1) {
        v.x += __shfl_down_sync(0xffffffffu, v.x, o);
        v.y += __shfl_down_sync(0xffffffffu, v.y, o);
        v.z += __shfl_down_sync(0xffffffffu, v.z, o);
        v.w += __shfl_down_sync(0xffffffffu, v.w, o);
    }
    if (lane == 0) sh[wid] = v;
    __syncthreads();
    float4 s = sh[0];
    #pragma unroll
    for (int w = 1; w < RT / 32; w++) {
        float4 t = sh[w];
        s.x += t.x; s.y += t.y; s.z += t.z; s.w += t.w;
    }
    __syncthreads();
    return s;
}

// split a pair of f32 into packed bf16 hi and exact-residual lo
__device__ __forceinline__ void pack2(float x0, float x1, unsigned& hi, unsigned& lo) {
    __nv_bfloat16 h0 = __float2bfloat16_rn(x0);
    __nv_bfloat16 h1 = __float2bfloat16_rn(x1);
    hi = (unsigned)__nv_bfloat16_raw(h0).x | ((unsigned)__nv_bfloat16_raw(h1).x << 16);
    __nv_bfloat16 l0 = __float2bfloat16_rn(x0 - __bfloat162float(h0));
    __nv_bfloat16 l1 = __float2bfloat16_rn(x1 - __bfloat162float(h1));
    lo = (unsigned)__nv_bfloat16_raw(l0).x | ((unsigned)__nv_bfloat16_raw(l1).x << 16);
}

// ---------------- kernel 0: label masks + row sigma ----------------
__global__ void __launch_bounds__(256) prep_kernel(const float* __restrict__ U,
                                                   const int* __restrict__ y) {
    int idx = blockIdx.x * 256 + threadIdx.x;     // NPTS*32 threads, one warp per U row
    int row = idx >> 5, w = idx & 31;
    float2 uu = *(const float2*)(U + (size_t)row * BITD + 2 * w);
    float s2 = fmaf(uu.x, uu.x, uu.y * uu.y);
    #pragma unroll
    for (int o = 16; o > 0; o >>= 1) s2 += __shfl_down_sync(0xffffffffu, s2, o);
    if ((idx & 31) == 0) {
        float sg = sqrtf(s2);
        g_sigR[row] = sg;
        g_sigI[row] = (sg > 1e-20f) ? __frcp_rn(sg) : 0.f;
    }
    if (idx < NPTS) {
        int j = idx, lane = j & 31;
        unsigned m = 0;
        #pragma unroll
        for (int l = 0; l < LLAB; l++) m |= (y[j * LLAB + l] != 0 ? 1u : 0u) << l;
        g_maskArr[j] = m;
        int word = j >> 5;
        #pragma unroll
        for (int b = 0; b < LLAB; b++) {
            unsigned bal = __ballot_sync(0xffffffffu, (m >> b) & 1u);
            if (lane == 0) g_Ybits[b * (NPTS / 32) + word] = bal;
        }
        if (j == 0) g_ctr = 0;
    }
}

// ---------------- bf16 mma wrapper (m16n8k16, f32 accum) ----------------
__device__ __forceinline__ void mma_bf16(float& c0, float& c1, float& c2, float& c3,
                                         unsigned a0, unsigned a1, unsigned a2, unsigned a3,
                                         unsigned b0, unsigned b1) {
    asm volatile(
        "mma.sync.aligned.m16n8k16.row.col.f32.bf16.bf16.f32 "
        "{%0,%1,%2,%3}, {%4,%5,%6,%7}, {%8,%9}, {%0,%1,%2,%3};"
        : "+f"(c0), "+f"(c1), "+f"(c2), "+f"(c3)
        : "r"(a0), "r"(a1), "r"(a2), "r"(a3), "r"(b0), "r"(b1));
}

// ---------------- kernel 1: inner = U @ V^T via split-bf16 tensor cores ----------------
// In-kernel conversion: each block splits its own 64-row U/V slices while staging.
__global__ void __launch_bounds__(256) gemm_kernel(const float* __restrict__ U,
                                                   const float* __restrict__ V) {
    __shared__ unsigned sAhi[64 * SPAD], sAlo[64 * SPAD];
    __shared__ unsigned sBhi[64 * SPAD], sBlo[64 * SPAD];

    int tid = threadIdx.x;
    int brow = blockIdx.y * 64, bcol = blockIdx.x * 64;

    #pragma unroll
    for (int it = 0; it < 2; it++) {
        int s = it * 256 + tid;            // 0..511 slots of 8 floats
        int r = s >> 3, c8 = (s & 7) * 8;
        int w0 = r * SPAD + (s & 7) * 4;
        const float* up = U + (size_t)(brow + r) * BITD + c8;
        float4 a0 = *(const float4*)(up);
        float4 a1 = *(const float4*)(up + 4);
        pack2(a0.x, a0.y, sAhi[w0 + 0], sAlo[w0 + 0]);
        pack2(a0.z, a0.w, sAhi[w0 + 1], sAlo[w0 + 1]);
        pack2(a1.x, a1.y, sAhi[w0 + 2], sAlo[w0 + 2]);
        pack2(a1.z, a1.w, sAhi[w0 + 3], sAlo[w0 + 3]);
        const float* vp = V + (size_t)(bcol + r) * BITD + c8;
        float4 b0 = *(const float4*)(vp);
        float4 b1 = *(const float4*)(vp + 4);
        pack2(b0.x, b0.y, sBhi[w0 + 0], sBlo[w0 + 0]);
        pack2(b0.z, b0.w, sBhi[w0 + 1], sBlo[w0 + 1]);
        pack2(b1.x, b1.y, sBhi[w0 + 2], sBlo[w0 + 2]);
        pack2(b1.z, b1.w, sBhi[w0 + 3], sBlo[w0 + 3]);
    }
    __syncthreads();

    int wpid = tid >> 5, lane = tid & 31;
    int warpRow = (wpid >> 1) * 16;
    int warpCol = (wpid & 1) * 32;
    int lr = lane >> 2, lc = lane & 3;

    float c[4][4];
    #pragma unroll
    for (int a = 0; a < 4; a++)
        #pragma unroll
        for (int k = 0; k < 4; k++) c[a][k] = 0.f;

    #pragma unroll
    for (int kc = 0; kc < 4; kc++) {
        int aw = kc * 8 + lc;
        int ar0 = (warpRow + lr) * SPAD, ar1 = (warpRow + lr + 8) * SPAD;
        unsigned ah0 = sAhi[ar0 + aw],     ah1 = sAhi[ar1 + aw];
        unsigned ah2 = sAhi[ar0 + aw + 4], ah3 = sAhi[ar1 + aw + 4];
        unsigned al0 = sAlo[ar0 + aw],     al1 = sAlo[ar1 + aw];
        unsigned al2 = sAlo[ar0 + aw + 4], al3 = sAlo[ar1 + aw + 4];
        #pragma unroll
        for (int ca = 0; ca < 4; ca++) {
            int bn = (warpCol + ca * 8 + lr) * SPAD;
            unsigned bh0 = sBhi[bn + aw], bh1 = sBhi[bn + aw + 4];
            unsigned bl0 = sBlo[bn + aw], bl1 = sBlo[bn + aw + 4];
            mma_bf16(c[ca][0], c[ca][1], c[ca][2], c[ca][3],
                     ah0, ah1, ah2, ah3, bh0, bh1);
            mma_bf16(c[ca][0], c[ca][1], c[ca][2], c[ca][3],
                     ah0, ah1, ah2, ah3, bl0, bl1);
            mma_bf16(c[ca][0], c[ca][1], c[ca][2], c[ca][3],
                     al0, al1, al2, al3, bh0, bh1);
        }
    }

    int r0 = brow + warpRow + lr;
    #pragma unroll
    for (int ca = 0; ca < 4; ca++) {
        int col = bcol + warpCol + ca * 8 + 2 * lc;
        *(float2*)(&g_inner[(size_t)r0 * NPTS + col]) = make_float2(c[ca][0], c[ca][1]);
        *(float2*)(&g_inner[(size_t)(r0 + 8) * NPTS + col]) = make_float2(c[ca][2], c[ca][3]);
    }
}

// ---------------- scan over packed 256-bin histogram, with totals ----------------
__device__ __forceinline__ void scan256(const unsigned* subH,
                                        unsigned rqS, unsigned rqD,
                                        unsigned* wsum, unsigned* brS, unsigned* brD,
                                        unsigned* totS, unsigned* totD) {
    int tid = threadIdx.x, lane = tid & 31, wid = tid >> 5;
    if (tid == 0) { brS[0] = 0u; brS[1] = 1u; brD[0] = 0u; brD[1] = 1u; }
    unsigned h = subH[tid];
    unsigned v = h;
    #pragma unroll
    for (int o = 1; o < 32; o <<= 1) {
        unsigned t = __shfl_up_sync(0xffffffffu, v, o);
        if (lane >= o) v += t;
    }
    if (lane == 31) wsum[wid] = v;
    __syncthreads();
    unsigned wb = 0, tot = 0;
    #pragma unroll
    for (int w = 0; w < RT / 32; w++) {
        unsigned t = wsum[w];
        if (w < wid) wb += t;
        tot += t;
    }
    unsigned incl = wb + v, excl = incl - h;
    unsigned inclS = incl & 0xFFFFu, exclS = excl & 0xFFFFu;
    unsigned inclD = incl >> 16,     exclD = excl >> 16;
    if (rqS > exclS && rqS <= inclS) { brS[0] = (unsigned)tid; brS[1] = rqS - exclS; }
    if (rqD > exclD && rqD <= inclD) { brD[0] = (unsigned)tid; brD[1] = rqD - exclD; }
    *totS = tot & 0xFFFFu;
    *totD = tot >> 16;
    __syncthreads();
}

// exact r-th smallest among c candidate keys (tie-aware counting select)
__device__ __forceinline__ void selectCount(const unsigned* cand, int c,
                                            unsigned r, unsigned* outT) {
    int tid = threadIdx.x;
    for (int idx = tid; idx < c; idx += RT) {
        unsigned mk = cand[idx];
        unsigned below = 0, eq = 0;
        for (int j = 0; j < c; j++) {
            unsigned k = cand[j];
            below += (k < mk); eq += (k == mk);
        }
        if (below < r && r <= below + eq) outT[0] = mk;
    }
    __syncthreads();
}

// ---------------- kernel 2: per-row loss (+ fused final reduction) ----------------
__global__ void __launch_bounds__(RT, 5) row_kernel(float* __restrict__ out) {
    __shared__ unsigned candS[CANDSZ], candD[CANDSZ];
    __shared__ unsigned subH[256];
    __shared__ unsigned wshA[RT / 32], wshB[RT / 32];
    __shared__ float4   fsh4[RT / 32];
    __shared__ unsigned brS[2], brD[2];
    __shared__ unsigned ccS, ccD, TkS, TkD;
    __shared__ int      lastFlag;

    int tid = threadIdx.x, lane = tid & 31, wid = tid >> 5;
    int i = blockIdx.x;

    subH[tid] = 0u;

    unsigned mi = g_maskArr[i];
    unsigned cls = 0;
    const unsigned short* yb = (const unsigned short*)g_Ybits;
    #pragma unroll
    for (int b = 0; b < LLAB; b++) {
        unsigned w = (unsigned)yb[b * (NPTS / 16) + tid];
        cls |= w & (0u - ((mi >> b) & 1u));
    }
    float sig  = g_sigR[i];
    float scS  = SCW * g_sigI[i];    // 0 when degenerate -> t = OFC >= 256 -> no bin

    const float* rowp = g_inner + (size_t)i * NPTS + tid * 16;
    float xv[16];
    #pragma unroll
    for (int q = 0; q < 4; q++) {
        float4 f = __ldcs((const float4*)(rowp + q * 4));
        xv[q * 4 + 0] = f.x; xv[q * 4 + 1] = f.y;
        xv[q * 4 + 2] = f.z; xv[q * 4 + 3] = f.w;
    }
    __syncthreads();   // subH cleared

    // merged pass: class sums + popcount + windowed histogram + below-window counts
    float sAll = 0.f, sS = 0.f;
    unsigned cb = 0;
    #pragma unroll
    for (int e = 0; e < 16; e++) {
        float x = xv[e];
        bool isS = (cls >> e) & 1u;
        sAll += x;
        if (isS) sS += x;
        float t = fmaf(isS ? x : -x, scS, OFC);   // S: [-2.4s,-0.5s]; D: [0.5s,2.4s]
        unsigned inc = isS ? 1u : 0x10000u;
        if (t < 0.f) cb += inc;
        else if (t < 256.0f) atomicAdd(&subH[(int)t], inc);
    }
    {
        #pragma unroll
        for (int o = 16; o > 0; o >>= 1) {
            sAll += __shfl_down_sync(0xffffffffu, sAll, o);
            sS   += __shfl_down_sync(0xffffffffu, sS, o);
        }
        unsigned pcw = __reduce_add_sync(0xffffffffu, __popc(cls));
        unsigned cbw = __reduce_add_sync(0xffffffffu, cb);
        if (lane == 0) {
            fsh4[wid] = make_float4(sAll, sS, 0.f, 0.f);
            wshA[wid] = pcw; wshB[wid] = cbw;
        }
    }
    __syncthreads();
    unsigned pc, cbt;
    {
        float4 fa = fsh4[0]; unsigned pct = wshA[0], cbx = wshB[0];
        #pragma unroll
        for (int w = 1; w < RT / 32; w++) {
            float4 ft = fsh4[w];
            fa.x += ft.x; fa.y += ft.y;
            pct += wshA[w]; cbx += wshB[w];
        }
        sAll = fa.x; sS = fa.y; pc = pct; cbt = cbx;
    }
    __syncthreads();

    int ns = (int)pc, nd = NPTS - ns;
    float sD = sAll - sS;
    int ksr = (ns * 9) / 10, kdr = (nd * 9) / 10;
    unsigned qS = (unsigned)(ns - ksr), qD = (unsigned)(nd - kdr);
    bool valid = (ns > 0) && (nd > 0);

    float rowres = 0.f;
    if (valid) {
        float muS = sS / (float)ns;
        float muD = sD / (float)nd;
        bool bigS = ns > SMALLN, bigD = nd > SMALLN;
        unsigned cbS = cbt & 0xFFFFu, cbD = cbt >> 16;

        unsigned totS, totD;
        scan256(subH, (bigS && qS > cbS) ? (qS - cbS) : 0u,
                      (bigD && qD > cbD) ? (qD - cbD) : 0u,
                wshA, brS, brD, &totS, &totD);
        bool okS = !bigS || ((qS > cbS) && (qS - cbS) <= totS);
        bool okD = !bigD || ((qD > cbD) && (qD - cbD) <= totD);
        unsigned binS = brS[0], binD = brD[0];
        unsigned rkS = (bigS && okS) ? brS[1] : qS;
        unsigned rkD = (bigD && okD) ? brD[1] : qD;
        float fscS = scS, fofS = OFC;
        float fscD = -scS, fofD = OFC;

        // attempt 2 (rare): exact class means, Chebyshev-safe +/-20 sigma window
        if ((bigS && !okS) || (bigD && !okD)) {
            bool aS = bigS && !okS, aD = bigD && !okD;
            float w2 = 40.f * sig;
            float sc2 = (w2 > 1e-30f) ? 256.f / w2 : 0.f;
            bool dg = (sc2 == 0.f);
            float of2S = -(muS - 20.f * sig) * sc2;
            float of2D = (muD + 20.f * sig) * sc2;
            subH[tid] = 0u;
            __syncthreads();
            unsigned cb2 = 0;
            #pragma unroll
            for (int e = 0; e < 16; e++) {
                float x = xv[e];
                bool isS = (cls >> e) & 1u;
                bool act = (isS ? aS : aD) && !dg;
                float t = fmaf(isS ? x : -x, sc2, isS ? of2S : of2D);
                unsigned inc = isS ? 1u : 0x10000u;
                if (act) {
                    if (t < 0.f) cb2 += inc;
                    else if (t < 256.0f) atomicAdd(&subH[(int)t], inc);
                }
            }
            cb2 = __reduce_add_sync(0xffffffffu, cb2);
            if (lane == 0) wshB[wid] = cb2;
            __syncthreads();
            unsigned c2t = 0;
            #pragma unroll
            for (int w = 0; w < RT / 32; w++) c2t += wshB[w];
            unsigned c2S = c2t & 0xFFFFu, c2D = c2t >> 16;
            unsigned t2S, t2D;
            scan256(subH, (aS && !dg && qS > c2S) ? (qS - c2S) : 0u,
                          (aD && !dg && qD > c2D) ? (qD - c2D) : 0u,
                    wshA, brS, brD, &t2S, &t2D);
            if (aS) {
                if (!dg && (qS > c2S) && (qS - c2S) <= t2S) {
                    binS = brS[0]; rkS = brS[1]; fscS = sc2; fofS = of2S;
                } else { fscS = 0.f; fofS = -1.f; }
            }
            if (aD) {
                if (!dg && (qD > c2D) && (qD - c2D) <= t2D) {
                    binD = brD[0]; rkD = brD[1]; fscD = -sc2; fofD = of2D;
                } else { fscD = 0.f; fofD = -1.f; }
            }
        }

        // compact candidates of located bins (small class: all elements)
        if (tid == 0) { ccS = 0u; ccD = 0u; TkS = fkey(muS); TkD = ~fkey(muD); }
        __syncthreads();
        #pragma unroll
        for (int e = 0; e < 16; e++) {
            float x = xv[e];
            bool isS = (cls >> e) & 1u;
            bool big = isS ? bigS : bigD;
            float t = fmaf(x, isS ? fscS : fscD, isS ? fofS : fofD);
            unsigned bsel = isS ? binS : binD;
            bool put = !big || (t >= 0.f && t < 256.0f && (unsigned)(int)t == bsel);
            if (put) {
                if (isS) {
                    unsigned idx = atomicAdd(&ccS, 1u);
                    if (idx < CANDSZ) candS[idx] = fkey(x);
                } else {
                    unsigned idx = atomicAdd(&ccD, 1u);
                    if (idx < CANDSZ) candD[idx] = ~fkey(x);
                }
            }
        }
        __syncthreads();
        selectCount(candS, (int)min(ccS, (unsigned)CANDSZ), rkS, &TkS);
        selectCount(candD, (int)min(ccD, (unsigned)CANDSZ), rkD, &TkD);
        float tsF = finv(TkS);
        float tdF = finv(~TkD);

        float sLS = 0.f, sLD = 0.f, cLS = 0.f, cLD = 0.f;
        #pragma unroll
        for (int e = 0; e < 16; e++) {
            float x = xv[e];
            bool isS = (cls >> e) & 1u;
            bool hit = isS ? (x < tsF) : (x > tdF);
            if (hit) {
                if (isS) { sLS += x; cLS += 1.f; }
                else     { sLD += x; cLD += 1.f; }
            }
        }
        float4 r1 = blockReduce4(make_float4(sLS, sLD, cLS, cLD), fsh4);
        float simMinSum = r1.x + ((float)qS - r1.z) * tsF;
        float disMaxSum = r1.y + ((float)qD - r1.w) * tdF;

        float similarMin    = simMinSum / (float)max((int)qS, 1);
        float dissimilarMax = disMaxSum / (float)max((int)qD, 1);
        float meanS  = fminf(fmaxf(muS, 0.f), UPPERB);
        float meanDS = fminf(fmaxf(muD, 0.f), UPPERB);

        float BP   = meanS  - (UPPERB - meanS) / UPPERB * fabsf(meanS - dissimilarMax);
        float BPds = meanDS - meanDS / UPPERB * fabsf(meanDS - similarMin);

        // softplus pass, algebraically reduced using ac = 2c:
        //   S: f = C*(z+min(z,0)), z = x-BP;    add softplus(f)
        //   D: -f_dis = C*(z+min(z,0)), z = BPds-x; add softplus(-f_dis)
        float pos = 0.f, nav = 0.f;
        #pragma unroll
        for (int e = 0; e < 16; e++) {
            float x = xv[e];
            bool isS = (cls >> e) & 1u;
            float z = isS ? (x - BP) : (BPds - x);
            float zz = z + fminf(z, 0.f);
            float f = CONST_C * zz;
            float sp = fmaxf(f, 0.f) + __logf(1.f + __expf(-fabsf(f)));
            if (isS) pos += sp; else nav += sp;
        }
        float4 r2 = blockReduce4(make_float4(pos, nav, 0.f, 0.f), fsh4);
        rowres = r2.x / (float)max(ns, 1) + r2.y / (float)max(nd, 1);
    }

    if (tid == 0) {
        g_rowout[i] = make_float2(valid ? rowres : 0.f, valid ? 1.f : 0.f);
        __threadfence();
        unsigned old = atomicAdd(&g_ctr, 1u);
        lastFlag = (old == NPTS - 1) ? 1 : 0;
    }
    __syncthreads();

    if (lastFlag) {
        __threadfence();
        float t = 0.f, c = 0.f;
        for (int idx = tid; idx < NPTS; idx += RT) {
            float2 rv = g_rowout[idx];
            t += rv.x; c += rv.y;
        }
        float4 r3 = blockReduce4(make_float4(t, c, 0.f, 0.f), fsh4);
        if (tid == 0) out[0] = (r3.y > 0.f) ? r3.x / fmaxf(r3.y, 1.f) : 0.f;
    }
}

// ---------------- launch ----------------
extern "C" void kernel_launch(void* const* d_in, const int* in_sizes, int n_in,
                              void* d_out, int out_size) {
    const float* u = (const float*)d_in[0];
    const float* v = (const float*)d_in[1];
    const int*   y = (const int*)d_in[2];

    prep_kernel<<<(NPTS * 32) / 256, 256>>>(u, y);
    dim3 gg(NPTS / 64, NPTS / 64);
    gemm_kernel<<<gg, 256>>>(u, v);
    row_kernel<<<NPTS, RT>>>((float*)d_out);
}

// round 13
// speedup vs baseline: 1.1197x; 1.1197x over previous
#include <cuda_runtime.h>
#include <cuda_bf16.h>
#include <math.h>

#define NPTS 4096
#define BITD 64
#define LLAB 10
#define RT   256
#define UPPERB 16.0f
// c = (1/right)*ln(yp/(99(1-yp))) with right=64/6, yp=0.5  -> -6*ln(99)/64
#define CONST_C    (-0.43079248594386178f)
#define CONST_AC   (-0.86158497188772356f)   // a*c, a = 2 exactly
#define CONST_BASE (0.0f)

#define CANDSZ 512
#define SMALLN 64
#define SCW    134.7368421f    // 256 / 1.9   (window width 1.9 sigma)
#define OFC    323.3684211f    // 2.4 * 256 / 1.9

#define KW   32          // 32 b32 words per row (64 bf16)
#define SPAD 36          // padded row stride in words

// ---------------- device scratch ----------------
__device__ float    g_inner[(size_t)NPTS * NPTS];   // 64 MB
__device__ unsigned g_maskArr[NPTS];
__device__ unsigned g_Ybits[LLAB * (NPTS / 32)];
__device__ float2   g_rowout[NPTS];
__device__ unsigned g_ctr;
__device__ float    g_sigR[NPTS];    // sigma = |u_i|
__device__ float    g_sigI[NPTS];    // 1/sigma (0 if degenerate)
__device__ __align__(16) unsigned g_Uhi[NPTS * KW];
__device__ __align__(16) unsigned g_Ulo[NPTS * KW];
__device__ __align__(16) unsigned g_Vhi[NPTS * KW];
__device__ __align__(16) unsigned g_Vlo[NPTS * KW];

// ---------------- helpers ----------------
__device__ __forceinline__ unsigned fkey(float f) {
    unsigned u = __float_as_uint(f);
    return u ^ (((unsigned)((int)u >> 31)) | 0x80000000u);
}
__device__ __forceinline__ float finv(unsigned k) {
    unsigned u = (k & 0x80000000u) ? (k ^ 0x80000000u) : ~k;
    return __uint_as_float(u);
}

__device__ __forceinline__ float4 blockReduce4(float4 v, float4* sh) {
    int tid = threadIdx.x, lane = tid & 31, wid = tid >> 5;
    #pragma unroll
    for (int o = 16; o > 0; o >>= 1) {
        v.x += __shfl_down_sync(0xffffffffu, v.x, o);
        v.y += __shfl_down_sync(0xffffffffu, v.y, o);
        v.z += __shfl_down_sync(0xffffffffu, v.z, o);
        v.w += __shfl_down_sync(0xffffffffu, v.w, o);
    }
    if (lane == 0) sh[wid] = v;
    __syncthreads();
    float4 s = sh[0];
    #pragma unroll
    for (int w = 1; w < RT / 32; w++) {
        float4 t = sh[w];
        s.x += t.x; s.y += t.y; s.z += t.z; s.w += t.w;
    }
    __syncthreads();
    return s;
}

__device__ __forceinline__ unsigned pack_hi(float x0, float x1) {
    __nv_bfloat16 h0 = __float2bfloat16_rn(x0);
    __nv_bfloat16 h1 = __float2bfloat16_rn(x1);
    unsigned r0 = (unsigned)__nv_bfloat16_raw(h0).x;
    unsigned r1 = (unsigned)__nv_bfloat16_raw(h1).x;
    return r0 | (r1 << 16);
}
__device__ __forceinline__ unsigned pack_lo(float x0, float x1) {
    __nv_bfloat16 h0 = __float2bfloat16_rn(x0);
    __nv_bfloat16 h1 = __float2bfloat16_rn(x1);
    __nv_bfloat16 l0 = __float2bfloat16_rn(x0 - __bfloat162float(h0));
    __nv_bfloat16 l1 = __float2bfloat16_rn(x1 - __bfloat162float(h1));
    unsigned r0 = (unsigned)__nv_bfloat16_raw(l0).x;
    unsigned r1 = (unsigned)__nv_bfloat16_raw(l1).x;
    return r0 | (r1 << 16);
}

// ---------------- kernel 0: split-bf16 conversion + masks + row sigma ----------------
__global__ void __launch_bounds__(256) prep_kernel(const float* __restrict__ U,
                                                   const float* __restrict__ V,
                                                   const int* __restrict__ y) {
    int idx = blockIdx.x * 256 + threadIdx.x;     // NPTS*32 threads, one warp per U row
    int row = idx >> 5, w = idx & 31;
    float2 uu = *(const float2*)(U + (size_t)row * BITD + 2 * w);
    float2 vv = *(const float2*)(V + (size_t)row * BITD + 2 * w);
    g_Uhi[row * KW + w] = pack_hi(uu.x, uu.y);
    g_Ulo[row * KW + w] = pack_lo(uu.x, uu.y);
    g_Vhi[row * KW + w] = pack_hi(vv.x, vv.y);
    g_Vlo[row * KW + w] = pack_lo(vv.x, vv.y);

    // sigma of row i's inner products = |u_i|  (labels independent of u,v)
    float s2 = fmaf(uu.x, uu.x, uu.y * uu.y);
    #pragma unroll
    for (int o = 16; o > 0; o >>= 1) s2 += __shfl_down_sync(0xffffffffu, s2, o);
    if ((idx & 31) == 0) {
        float sg = sqrtf(s2);
        g_sigR[row] = sg;
        g_sigI[row] = (sg > 1e-20f) ? __frcp_rn(sg) : 0.f;
    }

    if (idx < NPTS) {
        int j = idx, lane = j & 31;
        unsigned m = 0;
        #pragma unroll
        for (int l = 0; l < LLAB; l++) m |= (y[j * LLAB + l] != 0 ? 1u : 0u) << l;
        g_maskArr[j] = m;
        int word = j >> 5;
        #pragma unroll
        for (int b = 0; b < LLAB; b++) {
            unsigned bal = __ballot_sync(0xffffffffu, (m >> b) & 1u);
            if (lane == 0) g_Ybits[b * (NPTS / 32) + word] = bal;
        }
        if (j == 0) g_ctr = 0;
    }
}

// ---------------- bf16 mma wrapper (m16n8k16, f32 accum) ----------------
__device__ __forceinline__ void mma_bf16(float& c0, float& c1, float& c2, float& c3,
                                         unsigned a0, unsigned a1, unsigned a2, unsigned a3,
                                         unsigned b0, unsigned b1) {
    asm volatile(
        "mma.sync.aligned.m16n8k16.row.col.f32.bf16.bf16.f32 "
        "{%0,%1,%2,%3}, {%4,%5,%6,%7}, {%8,%9}, {%0,%1,%2,%3};"
        : "+f"(c0), "+f"(c1), "+f"(c2), "+f"(c3)
        : "r"(a0), "r"(a1), "r"(a2), "r"(a3), "r"(b0), "r"(b1));
}

// ---------------- kernel 1: inner = U @ V^T via split-bf16 tensor cores ----------------
__global__ void __launch_bounds__(256) gemm_kernel() {
    __shared__ unsigned sAhi[64 * SPAD], sAlo[64 * SPAD];
    __shared__ unsigned sBhi[64 * SPAD], sBlo[64 * SPAD];

    int tid = threadIdx.x;
    int brow = blockIdx.y * 64, bcol = blockIdx.x * 64;

    #pragma unroll
    for (int it = 0; it < 2; it++) {
        int s = it * 256 + tid;
        int r = s >> 3, j4 = (s & 7) * 4;
        size_t ga = (size_t)(brow + r) * KW + j4;
        size_t gb = (size_t)(bcol + r) * KW + j4;
        *(uint4*)(&sAhi[r * SPAD + j4]) = *(const uint4*)(&g_Uhi[ga]);
        *(uint4*)(&sAlo[r * SPAD + j4]) = *(const uint4*)(&g_Ulo[ga]);
        *(uint4*)(&sBhi[r * SPAD + j4]) = *(const uint4*)(&g_Vhi[gb]);
        *(uint4*)(&sBlo[r * SPAD + j4]) = *(const uint4*)(&g_Vlo[gb]);
    }
    __syncthreads();

    int wpid = tid >> 5, lane = tid & 31;
    int warpRow = (wpid >> 1) * 16;
    int warpCol = (wpid & 1) * 32;
    int lr = lane >> 2, lc = lane & 3;

    float c[4][4];
    #pragma unroll
    for (int a = 0; a < 4; a++)
        #pragma unroll
        for (int k = 0; k < 4; k++) c[a][k] = 0.f;

    #pragma unroll
    for (int kc = 0; kc < 4; kc++) {
        int aw = kc * 8 + lc;
        int ar0 = (warpRow + lr) * SPAD, ar1 = (warpRow + lr + 8) * SPAD;
        unsigned ah0 = sAhi[ar0 + aw],     ah1 = sAhi[ar1 + aw];
        unsigned ah2 = sAhi[ar0 + aw + 4], ah3 = sAhi[ar1 + aw + 4];
        unsigned al0 = sAlo[ar0 + aw],     al1 = sAlo[ar1 + aw];
        unsigned al2 = sAlo[ar0 + aw + 4], al3 = sAlo[ar1 + aw + 4];
        #pragma unroll
        for (int ca = 0; ca < 4; ca++) {
            int bn = (warpCol + ca * 8 + lr) * SPAD;
            unsigned bh0 = sBhi[bn + aw], bh1 = sBhi[bn + aw + 4];
            unsigned bl0 = sBlo[bn + aw], bl1 = sBlo[bn + aw + 4];
            mma_bf16(c[ca][0], c[ca][1], c[ca][2], c[ca][3],
                     ah0, ah1, ah2, ah3, bh0, bh1);
            mma_bf16(c[ca][0], c[ca][1], c[ca][2], c[ca][3],
                     ah0, ah1, ah2, ah3, bl0, bl1);
            mma_bf16(c[ca][0], c[ca][1], c[ca][2], c[ca][3],
                     al0, al1, al2, al3, bh0, bh1);
        }
    }

    int r0 = brow + warpRow + lr;
    #pragma unroll
    for (int ca = 0; ca < 4; ca++) {
        int col = bcol + warpCol + ca * 8 + 2 * lc;
        *(float2*)(&g_inner[(size_t)r0 * NPTS + col]) = make_float2(c[ca][0], c[ca][1]);
        *(float2*)(&g_inner[(size_t)(r0 + 8) * NPTS + col]) = make_float2(c[ca][2], c[ca][3]);
    }
}

// ---------------- scan over packed 256-bin histogram, with totals ----------------
__device__ __forceinline__ void scan256(const unsigned* subH,
                                        unsigned rqS, unsigned rqD,
                                        unsigned* wsum, unsigned* brS, unsigned* brD,
                                        unsigned* totS, unsigned* totD) {
    int tid = threadIdx.x, lane = tid & 31, wid = tid >> 5;
    if (tid == 0) { brS[0] = 0u; brS[1] = 1u; brD[0] = 0u; brD[1] = 1u; }
    unsigned h = subH[tid];
    unsigned v = h;
    #pragma unroll
    for (int o = 1; o < 32; o <<= 1) {
        unsigned t = __shfl_up_sync(0xffffffffu, v, o);
        if (lane >= o) v += t;
    }
    if (lane == 31) wsum[wid] = v;
    __syncthreads();
    unsigned wb = 0, tot = 0;
    #pragma unroll
    for (int w = 0; w < RT / 32; w++) {
        unsigned t = wsum[w];
        if (w < wid) wb += t;
        tot += t;
    }
    unsigned incl = wb + v, excl = incl - h;
    unsigned inclS = incl & 0xFFFFu, exclS = excl & 0xFFFFu;
    unsigned inclD = incl >> 16,     exclD = excl >> 16;
    if (rqS > exclS && rqS <= inclS) { brS[0] = (unsigned)tid; brS[1] = rqS - exclS; }
    if (rqD > exclD && rqD <= inclD) { brD[0] = (unsigned)tid; brD[1] = rqD - exclD; }
    *totS = tot & 0xFFFFu;
    *totD = tot >> 16;
    __syncthreads();
}

// exact r-th smallest among c candidate keys (tie-aware counting select)
__device__ __forceinline__ void selectCount(const unsigned* cand, int c,
                                            unsigned r, unsigned* outT) {
    int tid = threadIdx.x;
    for (int idx = tid; idx < c; idx += RT) {
        unsigned mk = cand[idx];
        unsigned below = 0, eq = 0;
        for (int j = 0; j < c; j++) {
            unsigned k = cand[j];
            below += (k < mk); eq += (k == mk);
        }
        if (below < r && r <= below + eq) outT[0] = mk;
    }
    __syncthreads();
}

// ---------------- kernel 2: per-row loss (+ fused final reduction) ----------------
__global__ void __launch_bounds__(RT, 5) row_kernel(float* __restrict__ out) {
    __shared__ unsigned candS[CANDSZ], candD[CANDSZ];
    __shared__ unsigned subH[256];
    __shared__ unsigned wshA[RT / 32], wshB[RT / 32];
    __shared__ float4   fsh4[RT / 32];
    __shared__ unsigned brS[2], brD[2];
    __shared__ unsigned ccS, ccD, TkS, TkD;
    __shared__ int      lastFlag;

    int tid = threadIdx.x, lane = tid & 31, wid = tid >> 5;
    int i = blockIdx.x;

    subH[tid] = 0u;

    unsigned mi = g_maskArr[i];
    unsigned cls = 0;
    const unsigned short* yb = (const unsigned short*)g_Ybits;
    #pragma unroll
    for (int b = 0; b < LLAB; b++) {
        unsigned w = (unsigned)yb[b * (NPTS / 16) + tid];
        cls |= w & (0u - ((mi >> b) & 1u));
    }
    float sig  = g_sigR[i];
    float scS  = SCW * g_sigI[i];    // 0 when degenerate -> t = OFC >= 256 -> no bin

    const float* rowp = g_inner + (size_t)i * NPTS + tid * 16;
    float xv[16];
    #pragma unroll
    for (int q = 0; q < 4; q++) {
        float4 f = __ldcs((const float4*)(rowp + q * 4));
        xv[q * 4 + 0] = f.x; xv[q * 4 + 1] = f.y;
        xv[q * 4 + 2] = f.z; xv[q * 4 + 3] = f.w;
    }
    __syncthreads();   // subH cleared

    // merged pass: class sums + popcount + windowed histogram + below-window counts
    float sAll = 0.f, sS = 0.f;
    unsigned cb = 0;
    #pragma unroll
    for (int e = 0; e < 16; e++) {
        float x = xv[e];
        bool isS = (cls >> e) & 1u;
        sAll += x;
        if (isS) sS += x;
        float t = fmaf(isS ? x : -x, scS, OFC);   // S: [-2.4s,-0.5s]; D: [0.5s,2.4s]
        unsigned inc = isS ? 1u : 0x10000u;
        if (t < 0.f) cb += inc;
        else if (t < 256.0f) atomicAdd(&subH[(int)t], inc);
    }
    {
        #pragma unroll
        for (int o = 16; o > 0; o >>= 1) {
            sAll += __shfl_down_sync(0xffffffffu, sAll, o);
            sS   += __shfl_down_sync(0xffffffffu, sS, o);
        }
        unsigned pcw = __reduce_add_sync(0xffffffffu, __popc(cls));
        unsigned cbw = __reduce_add_sync(0xffffffffu, cb);
        if (lane == 0) {
            fsh4[wid] = make_float4(sAll, sS, 0.f, 0.f);
            wshA[wid] = pcw; wshB[wid] = cbw;
        }
    }
    __syncthreads();
    unsigned pc, cbt;
    {
        float4 fa = fsh4[0]; unsigned pct = wshA[0], cbx = wshB[0];
        #pragma unroll
        for (int w = 1; w < RT / 32; w++) {
            float4 ft = fsh4[w];
            fa.x += ft.x; fa.y += ft.y;
            pct += wshA[w]; cbx += wshB[w];
        }
        sAll = fa.x; sS = fa.y; pc = pct; cbt = cbx;
    }
    __syncthreads();

    int ns = (int)pc, nd = NPTS - ns;
    float sD = sAll - sS;
    int ksr = (ns * 9) / 10, kdr = (nd * 9) / 10;
    unsigned qS = (unsigned)(ns - ksr), qD = (unsigned)(nd - kdr);
    bool valid = (ns > 0) && (nd > 0);

    float rowres = 0.f;
    if (valid) {
        float muS = sS / (float)ns;
        float muD = sD / (float)nd;
        bool bigS = ns > SMALLN, bigD = nd > SMALLN;
        unsigned cbS = cbt & 0xFFFFu, cbD = cbt >> 16;

        unsigned totS, totD;
        scan256(subH, (bigS && qS > cbS) ? (qS - cbS) : 0u,
                      (bigD && qD > cbD) ? (qD - cbD) : 0u,
                wshA, brS, brD, &totS, &totD);
        bool okS = !bigS || ((qS > cbS) && (qS - cbS) <= totS);
        bool okD = !bigD || ((qD > cbD) && (qD - cbD) <= totD);
        unsigned binS = brS[0], binD = brD[0];
        unsigned rkS = (bigS && okS) ? brS[1] : qS;
        unsigned rkD = (bigD && okD) ? brD[1] : qD;
        float fscS = scS, fofS = OFC;
        float fscD = -scS, fofD = OFC;

        // attempt 2 (rare): exact class means, Chebyshev-safe +/-20 sigma window
        if ((bigS && !okS) || (bigD && !okD)) {
            bool aS = bigS && !okS, aD = bigD && !okD;
            float w2 = 40.f * sig;
            float sc2 = (w2 > 1e-30f) ? 256.f / w2 : 0.f;
            bool dg = (sc2 == 0.f);
            float of2S = -(muS - 20.f * sig) * sc2;
            float of2D = (muD + 20.f * sig) * sc2;
            subH[tid] = 0u;
            __syncthreads();
            unsigned cb2 = 0;
            #pragma unroll
            for (int e = 0; e < 16; e++) {
                float x = xv[e];
                bool isS = (cls >> e) & 1u;
                bool act = (isS ? aS : aD) && !dg;
                float t = fmaf(isS ? x : -x, sc2, isS ? of2S : of2D);
                unsigned inc = isS ? 1u : 0x10000u;
                if (act) {
                    if (t < 0.f) cb2 += inc;
                    else if (t < 256.0f) atomicAdd(&subH[(int)t], inc);
                }
            }
            cb2 = __reduce_add_sync(0xffffffffu, cb2);
            if (lane == 0) wshB[wid] = cb2;
            __syncthreads();
            unsigned c2t = 0;
            #pragma unroll
            for (int w = 0; w < RT / 32; w++) c2t += wshB[w];
            unsigned c2S = c2t & 0xFFFFu, c2D = c2t >> 16;
            unsigned t2S, t2D;
            scan256(subH, (aS && !dg && qS > c2S) ? (qS - c2S) : 0u,
                          (aD && !dg && qD > c2D) ? (qD - c2D) : 0u,
                    wshA, brS, brD, &t2S, &t2D);
            if (aS) {
                if (!dg && (qS > c2S) && (qS - c2S) <= t2S) {
                    binS = brS[0]; rkS = brS[1]; fscS = sc2; fofS = of2S;
                } else { fscS = 0.f; fofS = -1.f; }
            }
            if (aD) {
                if (!dg && (qD > c2D) && (qD - c2D) <= t2D) {
                    binD = brD[0]; rkD = brD[1]; fscD = -sc2; fofD = of2D;
                } else { fscD = 0.f; fofD = -1.f; }
            }
        }

        // compact candidates of located bins (small class: all elements)
        if (tid == 0) { ccS = 0u; ccD = 0u; TkS = fkey(muS); TkD = ~fkey(muD); }
        __syncthreads();
        #pragma unroll
        for (int e = 0; e < 16; e++) {
            float x = xv[e];
            bool isS = (cls >> e) & 1u;
            bool big = isS ? bigS : bigD;
            float t = fmaf(x, isS ? fscS : fscD, isS ? fofS : fofD);
            unsigned bsel = isS ? binS : binD;
            bool put = !big || (t >= 0.f && t < 256.0f && (unsigned)(int)t == bsel);
            if (put) {
                if (isS) {
                    unsigned idx = atomicAdd(&ccS, 1u);
                    if (idx < CANDSZ) candS[idx] = fkey(x);
                } else {
                    unsigned idx = atomicAdd(&ccD, 1u);
                    if (idx < CANDSZ) candD[idx] = ~fkey(x);
                }
            }
        }
        __syncthreads();
        selectCount(candS, (int)min(ccS, (unsigned)CANDSZ), rkS, &TkS);
        selectCount(candD, (int)min(ccD, (unsigned)CANDSZ), rkD, &TkD);
        float tsF = finv(TkS);
        float tdF = finv(~TkD);

        float sLS = 0.f, sLD = 0.f, cLS = 0.f, cLD = 0.f;
        #pragma unroll
        for (int e = 0; e < 16; e++) {
            float x = xv[e];
            bool isS = (cls >> e) & 1u;
            bool hit = isS ? (x < tsF) : (x > tdF);
            if (hit) {
                if (isS) { sLS += x; cLS += 1.f; }
                else     { sLD += x; cLD += 1.f; }
            }
        }
        float4 r1 = blockReduce4(make_float4(sLS, sLD, cLS, cLD), fsh4);
        float simMinSum = r1.x + ((float)qS - r1.z) * tsF;
        float disMaxSum = r1.y + ((float)qD - r1.w) * tdF;

        float similarMin    = simMinSum / (float)max((int)qS, 1);
        float dissimilarMax = disMaxSum / (float)max((int)qD, 1);
        float meanS  = fminf(fmaxf(muS, 0.f), UPPERB);
        float meanDS = fminf(fmaxf(muD, 0.f), UPPERB);

        float BP   = meanS  - (UPPERB - meanS) / UPPERB * fabsf(meanS - dissimilarMax);
        float BPds = meanDS - meanDS / UPPERB * fabsf(meanDS - similarMin);

        // softplus pass, algebraically reduced using ac = 2c:
        //   S: f = C*(z+min(z,0)), z = x-BP;    add softplus(f)
        //   D: -f_dis = C*(z+min(z,0)), z = BPds-x; add softplus(-f_dis)
        float pos = 0.f, nav = 0.f;
        #pragma unroll
        for (int e = 0; e < 16; e++) {
            float x = xv[e];
            bool isS = (cls >> e) & 1u;
            float z = isS ? (x - BP) : (BPds - x);
            float zz = z + fminf(z, 0.f);
            float f = CONST_C * zz;
            float sp = fmaxf(f, 0.f) + __logf(1.f + __expf(-fabsf(f)));
            if (isS) pos += sp; else nav += sp;
        }
        float4 r2 = blockReduce4(make_float4(pos, nav, 0.f, 0.f), fsh4);
        rowres = r2.x / (float)max(ns, 1) + r2.y / (float)max(nd, 1);
    }

    if (tid == 0) {
        g_rowout[i] = make_float2(valid ? rowres : 0.f, valid ? 1.f : 0.f);
        __threadfence();
        unsigned old = atomicAdd(&g_ctr, 1u);
        lastFlag = (old == NPTS - 1) ? 1 : 0;
    }
    __syncthreads();

    if (lastFlag) {
        __threadfence();
        float t = 0.f, c = 0.f;
        for (int idx = tid; idx < NPTS; idx += RT) {
            float2 rv = g_rowout[idx];
            t += rv.x; c += rv.y;
        }
        float4 r3 = blockReduce4(make_float4(t, c, 0.f, 0.f), fsh4);
        if (tid == 0) out[0] = (r3.y > 0.f) ? r3.x / fmaxf(r3.y, 1.f) : 0.f;
    }
}

// ---------------- launch ----------------
extern "C" void kernel_launch(void* const* d_in, const int* in_sizes, int n_in,
                              void* d_out, int out_size) {
    const float* u = (const float*)d_in[0];
    const float* v = (const float*)d_in[1];
    const int*   y = (const int*)d_in[2];

    prep_kernel<<<(NPTS * KW) / 256, 256>>>(u, v, y);
    dim3 gg(NPTS / 64, NPTS / 64);
    gemm_kernel<<<gg, 256>>>();
    row_kernel<<<NPTS, RT>>>((float*)d_out);
}

// round 14
// speedup vs baseline: 1.1419x; 1.0199x over previous
#include <cuda_runtime.h>
#include <cuda_bf16.h>
#include <math.h>

#define NPTS 4096
#define BITD 64
#define LLAB 10
#define RT   256
#define UPPERB 16.0f
// c = (1/right)*ln(yp/(99(1-yp))) with right=64/6, yp=0.5  -> -6*ln(99)/64
#define CONST_C    (-0.43079248594386178f)
#define CONST_AC   (-0.86158497188772356f)   // a*c, a = 2 exactly
#define CONST_BASE (0.0f)

#define CANDSZ 512
#define SMALLN 64
#define SCW    134.7368421f    // 256 / 1.9   (window width 1.9 sigma)
#define OFC    323.3684211f    // 2.4 * 256 / 1.9

#define KW   32          // 32 b32 words per row (64 bf16)
#define SPAD 36          // padded row stride in words

// ---------------- device scratch ----------------
__device__ __nv_bfloat16 g_innerB[(size_t)NPTS * NPTS];   // 32 MB
__device__ unsigned g_maskArr[NPTS];
__device__ unsigned g_Ybits[LLAB * (NPTS / 32)];
__device__ float2   g_rowout[NPTS];
__device__ unsigned g_ctr;
__device__ float    g_sigR[NPTS];    // sigma = |u_i|
__device__ float    g_sigI[NPTS];    // 1/sigma (0 if degenerate)
__device__ __align__(16) unsigned g_Uhi[NPTS * KW];
__device__ __align__(16) unsigned g_Ulo[NPTS * KW];
__device__ __align__(16) unsigned g_Vhi[NPTS * KW];
__device__ __align__(16) unsigned g_Vlo[NPTS * KW];

// ---------------- helpers ----------------
__device__ __forceinline__ unsigned fkey(float f) {
    unsigned u = __float_as_uint(f);
    return u ^ (((unsigned)((int)u >> 31)) | 0x80000000u);
}
__device__ __forceinline__ float finv(unsigned k) {
    unsigned u = (k & 0x80000000u) ? (k ^ 0x80000000u) : ~k;
    return __uint_as_float(u);
}

__device__ __forceinline__ float4 blockReduce4(float4 v, float4* sh) {
    int tid = threadIdx.x, lane = tid & 31, wid = tid >> 5;
    #pragma unroll
    for (int o = 16; o > 0; o >>= 1) {
        v.x += __shfl_down_sync(0xffffffffu, v.x, o);
        v.y += __shfl_down_sync(0xffffffffu, v.y, o);
        v.z += __shfl_down_sync(0xffffffffu, v.z, o);
        v.w += __shfl_down_sync(0xffffffffu, v.w, o);
    }
    if (lane == 0) sh[wid] = v;
    __syncthreads();
    float4 s = sh[0];
    #pragma unroll
    for (int w = 1; w < RT / 32; w++) {
        float4 t = sh[w];
        s.x += t.x; s.y += t.y; s.z += t.z; s.w += t.w;
    }
    __syncthreads();
    return s;
}

__device__ __forceinline__ unsigned pack_hi(float x0, float x1) {
    __nv_bfloat16 h0 = __float2bfloat16_rn(x0);
    __nv_bfloat16 h1 = __float2bfloat16_rn(x1);
    unsigned r0 = (unsigned)__nv_bfloat16_raw(h0).x;
    unsigned r1 = (unsigned)__nv_bfloat16_raw(h1).x;
    return r0 | (r1 << 16);
}
__device__ __forceinline__ unsigned pack_lo(float x0, float x1) {
    __nv_bfloat16 h0 = __float2bfloat16_rn(x0);
    __nv_bfloat16 h1 = __float2bfloat16_rn(x1);
    __nv_bfloat16 l0 = __float2bfloat16_rn(x0 - __bfloat162float(h0));
    __nv_bfloat16 l1 = __float2bfloat16_rn(x1 - __bfloat162float(h1));
    unsigned r0 = (unsigned)__nv_bfloat16_raw(l0).x;
    unsigned r1 = (unsigned)__nv_bfloat16_raw(l1).x;
    return r0 | (r1 << 16);
}

// ---------------- kernel 0: split-bf16 conversion + masks + row sigma ----------------
__global__ void __launch_bounds__(256) prep_kernel(const float* __restrict__ U,
                                                   const float* __restrict__ V,
                                                   const int* __restrict__ y) {
    int idx = blockIdx.x * 256 + threadIdx.x;     // NPTS*32 threads, one warp per U row
    int row = idx >> 5, w = idx & 31;
    float2 uu = *(const float2*)(U + (size_t)row * BITD + 2 * w);
    float2 vv = *(const float2*)(V + (size_t)row * BITD + 2 * w);
    g_Uhi[row * KW + w] = pack_hi(uu.x, uu.y);
    g_Ulo[row * KW + w] = pack_lo(uu.x, uu.y);
    g_Vhi[row * KW + w] = pack_hi(vv.x, vv.y);
    g_Vlo[row * KW + w] = pack_lo(vv.x, vv.y);

    float s2 = fmaf(uu.x, uu.x, uu.y * uu.y);
    #pragma unroll
    for (int o = 16; o > 0; o >>= 1) s2 += __shfl_down_sync(0xffffffffu, s2, o);
    if ((idx & 31) == 0) {
        float sg = sqrtf(s2);
        g_sigR[row] = sg;
        g_sigI[row] = (sg > 1e-20f) ? __frcp_rn(sg) : 0.f;
    }

    if (idx < NPTS) {
        int j = idx, lane = j & 31;
        unsigned m = 0;
        #pragma unroll
        for (int l = 0; l < LLAB; l++) m |= (y[j * LLAB + l] != 0 ? 1u : 0u) << l;
        g_maskArr[j] = m;
        int word = j >> 5;
        #pragma unroll
        for (int b = 0; b < LLAB; b++) {
            unsigned bal = __ballot_sync(0xffffffffu, (m >> b) & 1u);
            if (lane == 0) g_Ybits[b * (NPTS / 32) + word] = bal;
        }
        if (j == 0) g_ctr = 0;
    }
}

// ---------------- bf16 mma wrapper (m16n8k16, f32 accum) ----------------
__device__ __forceinline__ void mma_bf16(float& c0, float& c1, float& c2, float& c3,
                                         unsigned a0, unsigned a1, unsigned a2, unsigned a3,
                                         unsigned b0, unsigned b1) {
    asm volatile(
        "mma.sync.aligned.m16n8k16.row.col.f32.bf16.bf16.f32 "
        "{%0,%1,%2,%3}, {%4,%5,%6,%7}, {%8,%9}, {%0,%1,%2,%3};"
        : "+f"(c0), "+f"(c1), "+f"(c2), "+f"(c3)
        : "r"(a0), "r"(a1), "r"(a2), "r"(a3), "r"(b0), "r"(b1));
}

// ---------------- kernel 1: inner = U @ V^T via split-bf16 tensor cores ----------------
__global__ void __launch_bounds__(256) gemm_kernel() {
    __shared__ unsigned sAhi[64 * SPAD], sAlo[64 * SPAD];
    __shared__ unsigned sBhi[64 * SPAD], sBlo[64 * SPAD];

    int tid = threadIdx.x;
    int brow = blockIdx.y * 64, bcol = blockIdx.x * 64;

    #pragma unroll
    for (int it = 0; it < 2; it++) {
        int s = it * 256 + tid;
        int r = s >> 3, j4 = (s & 7) * 4;
        size_t ga = (size_t)(brow + r) * KW + j4;
        size_t gb = (size_t)(bcol + r) * KW + j4;
        *(uint4*)(&sAhi[r * SPAD + j4]) = *(const uint4*)(&g_Uhi[ga]);
        *(uint4*)(&sAlo[r * SPAD + j4]) = *(const uint4*)(&g_Ulo[ga]);
        *(uint4*)(&sBhi[r * SPAD + j4]) = *(const uint4*)(&g_Vhi[gb]);
        *(uint4*)(&sBlo[r * SPAD + j4]) = *(const uint4*)(&g_Vlo[gb]);
    }
    __syncthreads();

    int wpid = tid >> 5, lane = tid & 31;
    int warpRow = (wpid >> 1) * 16;
    int warpCol = (wpid & 1) * 32;
    int lr = lane >> 2, lc = lane & 3;

    float c[4][4];
    #pragma unroll
    for (int a = 0; a < 4; a++)
        #pragma unroll
        for (int k = 0; k < 4; k++) c[a][k] = 0.f;

    #pragma unroll
    for (int kc = 0; kc < 4; kc++) {
        int aw = kc * 8 + lc;
        int ar0 = (warpRow + lr) * SPAD, ar1 = (warpRow + lr + 8) * SPAD;
        unsigned ah0 = sAhi[ar0 + aw],     ah1 = sAhi[ar1 + aw];
        unsigned ah2 = sAhi[ar0 + aw + 4], ah3 = sAhi[ar1 + aw + 4];
        unsigned al0 = sAlo[ar0 + aw],     al1 = sAlo[ar1 + aw];
        unsigned al2 = sAlo[ar0 + aw + 4], al3 = sAlo[ar1 + aw + 4];
        #pragma unroll
        for (int ca = 0; ca < 4; ca++) {
            int bn = (warpCol + ca * 8 + lr) * SPAD;
            unsigned bh0 = sBhi[bn + aw], bh1 = sBhi[bn + aw + 4];
            unsigned bl0 = sBlo[bn + aw], bl1 = sBlo[bn + aw + 4];
            mma_bf16(c[ca][0], c[ca][1], c[ca][2], c[ca][3],
                     ah0, ah1, ah2, ah3, bh0, bh1);
            mma_bf16(c[ca][0], c[ca][1], c[ca][2], c[ca][3],
                     ah0, ah1, ah2, ah3, bl0, bl1);
            mma_bf16(c[ca][0], c[ca][1], c[ca][2], c[ca][3],
                     al0, al1, al2, al3, bh0, bh1);
        }
    }

    // store C as bf16 (halves the DRAM write stream)
    int r0 = brow + warpRow + lr;
    #pragma unroll
    for (int ca = 0; ca < 4; ca++) {
        int col = bcol + warpCol + ca * 8 + 2 * lc;   // even -> u32-aligned
        __nv_bfloat162 p0 = __float22bfloat162_rn(make_float2(c[ca][0], c[ca][1]));
        __nv_bfloat162 p1 = __float22bfloat162_rn(make_float2(c[ca][2], c[ca][3]));
        *(__nv_bfloat162*)(&g_innerB[(size_t)r0 * NPTS + col]) = p0;
        *(__nv_bfloat162*)(&g_innerB[(size_t)(r0 + 8) * NPTS + col]) = p1;
    }
}

// ---------------- scan over packed 256-bin histogram, with totals ----------------
__device__ __forceinline__ void scan256(const unsigned* subH,
                                        unsigned rqS, unsigned rqD,
                                        unsigned* wsum, unsigned* brS, unsigned* brD,
                                        unsigned* totS, unsigned* totD) {
    int tid = threadIdx.x, lane = tid & 31, wid = tid >> 5;
    if (tid == 0) { brS[0] = 0u; brS[1] = 1u; brD[0] = 0u; brD[1] = 1u; }
    unsigned h = subH[tid];
    unsigned v = h;
    #pragma unroll
    for (int o = 1; o < 32; o <<= 1) {
        unsigned t = __shfl_up_sync(0xffffffffu, v, o);
        if (lane >= o) v += t;
    }
    if (lane == 31) wsum[wid] = v;
    __syncthreads();
    unsigned wb = 0, tot = 0;
    #pragma unroll
    for (int w = 0; w < RT / 32; w++) {
        unsigned t = wsum[w];
        if (w < wid) wb += t;
        tot += t;
    }
    unsigned incl = wb + v, excl = incl - h;
    unsigned inclS = incl & 0xFFFFu, exclS = excl & 0xFFFFu;
    unsigned inclD = incl >> 16,     exclD = excl >> 16;
    if (rqS > exclS && rqS <= inclS) { brS[0] = (unsigned)tid; brS[1] = rqS - exclS; }
    if (rqD > exclD && rqD <= inclD) { brD[0] = (unsigned)tid; brD[1] = rqD - exclD; }
    *totS = tot & 0xFFFFu;
    *totD = tot >> 16;
    __syncthreads();
}

// exact r-th smallest among c candidate keys (tie-aware counting select)
__device__ __forceinline__ void selectCount(const unsigned* cand, int c,
                                            unsigned r, unsigned* outT) {
    int tid = threadIdx.x;
    for (int idx = tid; idx < c; idx += RT) {
        unsigned mk = cand[idx];
        unsigned below = 0, eq = 0;
        for (int j = 0; j < c; j++) {
            unsigned k = cand[j];
            below += (k < mk); eq += (k == mk);
        }
        if (below < r && r <= below + eq) outT[0] = mk;
    }
    __syncthreads();
}

// ---------------- kernel 2: per-row loss (+ fused final reduction) ----------------
__global__ void __launch_bounds__(RT, 5) row_kernel(float* __restrict__ out) {
    __shared__ unsigned candS[CANDSZ], candD[CANDSZ];
    __shared__ unsigned subH[256];
    __shared__ unsigned wshA[RT / 32], wshB[RT / 32];
    __shared__ float4   fsh4[RT / 32];
    __shared__ unsigned brS[2], brD[2];
    __shared__ unsigned ccS, ccD, TkS, TkD;
    __shared__ int      lastFlag;

    int tid = threadIdx.x, lane = tid & 31, wid = tid >> 5;
    int i = blockIdx.x;

    subH[tid] = 0u;

    unsigned mi = g_maskArr[i];
    unsigned cls = 0;
    const unsigned short* yb = (const unsigned short*)g_Ybits;
    #pragma unroll
    for (int b = 0; b < LLAB; b++) {
        unsigned w = (unsigned)yb[b * (NPTS / 16) + tid];
        cls |= w & (0u - ((mi >> b) & 1u));
    }
    float sig  = g_sigR[i];
    float scS  = SCW * g_sigI[i];    // 0 when degenerate -> t = OFC >= 256 -> no bin

    // load 16 bf16 values, expand to f32
    const uint4* rp = (const uint4*)(g_innerB + (size_t)i * NPTS + tid * 16);
    uint4 p0 = __ldcs(rp);
    uint4 p1 = __ldcs(rp + 1);
    float xv[16];
    {
        unsigned wds[8] = {p0.x, p0.y, p0.z, p0.w, p1.x, p1.y, p1.z, p1.w};
        #pragma unroll
        for (int q = 0; q < 8; q++) {
            __nv_bfloat162 h = *(__nv_bfloat162*)&wds[q];
            float2 f = __bfloat1622float2(h);
            xv[q * 2 + 0] = f.x;
            xv[q * 2 + 1] = f.y;
        }
    }
    __syncthreads();   // subH cleared

    // merged pass: class sums + popcount + windowed histogram + below-window counts
    float sAll = 0.f, sS = 0.f;
    unsigned cb = 0;
    #pragma unroll
    for (int e = 0; e < 16; e++) {
        float x = xv[e];
        bool isS = (cls >> e) & 1u;
        sAll += x;
        if (isS) sS += x;
        float t = fmaf(isS ? x : -x, scS, OFC);   // S: [-2.4s,-0.5s]; D: [0.5s,2.4s]
        unsigned inc = isS ? 1u : 0x10000u;
        if (t < 0.f) cb += inc;
        else if (t < 256.0f) atomicAdd(&subH[(int)t], inc);
    }
    {
        #pragma unroll
        for (int o = 16; o > 0; o >>= 1) {
            sAll += __shfl_down_sync(0xffffffffu, sAll, o);
            sS   += __shfl_down_sync(0xffffffffu, sS, o);
        }
        unsigned pcw = __reduce_add_sync(0xffffffffu, __popc(cls));
        unsigned cbw = __reduce_add_sync(0xffffffffu, cb);
        if (lane == 0) {
            fsh4[wid] = make_float4(sAll, sS, 0.f, 0.f);
            wshA[wid] = pcw; wshB[wid] = cbw;
        }
    }
    __syncthreads();
    unsigned pc, cbt;
    {
        float4 fa = fsh4[0]; unsigned pct = wshA[0], cbx = wshB[0];
        #pragma unroll
        for (int w = 1; w < RT / 32; w++) {
            float4 ft = fsh4[w];
            fa.x += ft.x; fa.y += ft.y;
            pct += wshA[w]; cbx += wshB[w];
        }
        sAll = fa.x; sS = fa.y; pc = pct; cbt = cbx;
    }
    __syncthreads();

    int ns = (int)pc, nd = NPTS - ns;
    float sD = sAll - sS;
    int ksr = (ns * 9) / 10, kdr = (nd * 9) / 10;
    unsigned qS = (unsigned)(ns - ksr), qD = (unsigned)(nd - kdr);
    bool valid = (ns > 0) && (nd > 0);

    float rowres = 0.f;
    if (valid) {
        float muS = sS / (float)ns;
        float muD = sD / (float)nd;
        bool bigS = ns > SMALLN, bigD = nd > SMALLN;
        unsigned cbS = cbt & 0xFFFFu, cbD = cbt >> 16;

        unsigned totS, totD;
        scan256(subH, (bigS && qS > cbS) ? (qS - cbS) : 0u,
                      (bigD && qD > cbD) ? (qD - cbD) : 0u,
                wshA, brS, brD, &totS, &totD);
        bool okS = !bigS || ((qS > cbS) && (qS - cbS) <= totS);
        bool okD = !bigD || ((qD > cbD) && (qD - cbD) <= totD);
        unsigned binS = brS[0], binD = brD[0];
        unsigned rkS = (bigS && okS) ? brS[1] : qS;
        unsigned rkD = (bigD && okD) ? brD[1] : qD;
        float fscS = scS, fofS = OFC;
        float fscD = -scS, fofD = OFC;

        // attempt 2 (rare): exact class means, Chebyshev-safe +/-20 sigma window
        if ((bigS && !okS) || (bigD && !okD)) {
            bool aS = bigS && !okS, aD = bigD && !okD;
            float w2 = 40.f * sig;
            float sc2 = (w2 > 1e-30f) ? 256.f / w2 : 0.f;
            bool dg = (sc2 == 0.f);
            float of2S = -(muS - 20.f * sig) * sc2;
            float of2D = (muD + 20.f * sig) * sc2;
            subH[tid] = 0u;
            __syncthreads();
            unsigned cb2 = 0;
            #pragma unroll
            for (int e = 0; e < 16; e++) {
                float x = xv[e];
                bool isS = (cls >> e) & 1u;
                bool act = (isS ? aS : aD) && !dg;
                float t = fmaf(isS ? x : -x, sc2, isS ? of2S : of2D);
                unsigned inc = isS ? 1u : 0x10000u;
                if (act) {
                    if (t < 0.f) cb2 += inc;
                    else if (t < 256.0f) atomicAdd(&subH[(int)t], inc);
                }
            }
            cb2 = __reduce_add_sync(0xffffffffu, cb2);
            if (lane == 0) wshB[wid] = cb2;
            __syncthreads();
            unsigned c2t = 0;
            #pragma unroll
            for (int w = 0; w < RT / 32; w++) c2t += wshB[w];
            unsigned c2S = c2t & 0xFFFFu, c2D = c2t >> 16;
            unsigned t2S, t2D;
            scan256(subH, (aS && !dg && qS > c2S) ? (qS - c2S) : 0u,
                          (aD && !dg && qD > c2D) ? (qD - c2D) : 0u,
                    wshA, brS, brD, &t2S, &t2D);
            if (aS) {
                if (!dg && (qS > c2S) && (qS - c2S) <= t2S) {
                    binS = brS[0]; rkS = brS[1]; fscS = sc2; fofS = of2S;
                } else { fscS = 0.f; fofS = -1.f; }
            }
            if (aD) {
                if (!dg && (qD > c2D) && (qD - c2D) <= t2D) {
                    binD = brD[0]; rkD = brD[1]; fscD = -sc2; fofD = of2D;
                } else { fscD = 0.f; fofD = -1.f; }
            }
        }

        // compact candidates of located bins (small class: all elements)
        if (tid == 0) { ccS = 0u; ccD = 0u; TkS = fkey(muS); TkD = ~fkey(muD); }
        __syncthreads();
        #pragma unroll
        for (int e = 0; e < 16; e++) {
            float x = xv[e];
            bool isS = (cls >> e) & 1u;
            bool big = isS ? bigS : bigD;
            float t = fmaf(x, isS ? fscS : fscD, isS ? fofS : fofD);
            unsigned bsel = isS ? binS : binD;
            bool put = !big || (t >= 0.f && t < 256.0f && (unsigned)(int)t == bsel);
            if (put) {
                if (isS) {
                    unsigned idx = atomicAdd(&ccS, 1u);
                    if (idx < CANDSZ) candS[idx] = fkey(x);
                } else {
                    unsigned idx = atomicAdd(&ccD, 1u);
                    if (idx < CANDSZ) candD[idx] = ~fkey(x);
                }
            }
        }
        __syncthreads();
        selectCount(candS, (int)min(ccS, (unsigned)CANDSZ), rkS, &TkS);
        selectCount(candD, (int)min(ccD, (unsigned)CANDSZ), rkD, &TkD);
        float tsF = finv(TkS);
        float tdF = finv(~TkD);

        float sLS = 0.f, sLD = 0.f, cLS = 0.f, cLD = 0.f;
        #pragma unroll
        for (int e = 0; e < 16; e++) {
            float x = xv[e];
            bool isS = (cls >> e) & 1u;
            bool hit = isS ? (x < tsF) : (x > tdF);
            if (hit) {
                if (isS) { sLS += x; cLS += 1.f; }
                else     { sLD += x; cLD += 1.f; }
            }
        }
        float4 r1 = blockReduce4(make_float4(sLS, sLD, cLS, cLD), fsh4);
        float simMinSum = r1.x + ((float)qS - r1.z) * tsF;
        float disMaxSum = r1.y + ((float)qD - r1.w) * tdF;

        float similarMin    = simMinSum / (float)max((int)qS, 1);
        float dissimilarMax = disMaxSum / (float)max((int)qD, 1);
        float meanS  = fminf(fmaxf(muS, 0.f), UPPERB);
        float meanDS = fminf(fmaxf(muD, 0.f), UPPERB);

        float BP   = meanS  - (UPPERB - meanS) / UPPERB * fabsf(meanS - dissimilarMax);
        float BPds = meanDS - meanDS / UPPERB * fabsf(meanDS - similarMin);

        // softplus pass (ac = 2c): f = C*(z+min(z,0))
        float pos = 0.f, nav = 0.f;
        #pragma unroll
        for (int e = 0; e < 16; e++) {
            float x = xv[e];
            bool isS = (cls >> e) & 1u;
            float z = isS ? (x - BP) : (BPds - x);
            float zz = z + fminf(z, 0.f);
            float f = CONST_C * zz;
            float sp = fmaxf(f, 0.f) + __logf(1.f + __expf(-fabsf(f)));
            if (isS) pos += sp; else nav += sp;
        }
        float4 r2 = blockReduce4(make_float4(pos, nav, 0.f, 0.f), fsh4);
        rowres = r2.x / (float)max(ns, 1) + r2.y / (float)max(nd, 1);
    }

    if (tid == 0) {
        g_rowout[i] = make_float2(valid ? rowres : 0.f, valid ? 1.f : 0.f);
        __threadfence();
        unsigned old = atomicAdd(&g_ctr, 1u);
        lastFlag = (old == NPTS - 1) ? 1 : 0;
    }
    __syncthreads();

    if (lastFlag) {
        __threadfence();
        float t = 0.f, c = 0.f;
        for (int idx = tid; idx < NPTS; idx += RT) {
            float2 rv = g_rowout[idx];
            t += rv.x; c += rv.y;
        }
        float4 r3 = blockReduce4(make_float4(t, c, 0.f, 0.f), fsh4);
        if (tid == 0) out[0] = (r3.y > 0.f) ? r3.x / fmaxf(r3.y, 1.f) : 0.f;
    }
}

// ---------------- launch ----------------
extern "C" void kernel_launch(void* const* d_in, const int* in_sizes, int n_in,
                              void* d_out, int out_size) {
    const float* u = (const float*)d_in[0];
    const float* v = (const float*)d_in[1];
    const int*   y = (const int*)d_in[2];

    prep_kernel<<<(NPTS * KW) / 256, 256>>>(u, v, y);
    dim3 gg(NPTS / 64, NPTS / 64);
    gemm_kernel<<<gg, 256>>>();
    row_kernel<<<NPTS, RT>>>((float*)d_out);
}

// round 15
// speedup vs baseline: 1.2156x; 1.0645x over previous
#include <cuda_runtime.h>
#include <cuda_bf16.h>
#include <math.h>

#define NPTS 4096
#define BITD 64
#define LLAB 10
#define RT   256
#define UPPERB 16.0f
// c = (1/right)*ln(yp/(99(1-yp))) with right=64/6, yp=0.5  -> -6*ln(99)/64
#define CONST_C    (-0.43079248594386178f)
#define CONST_AC   (-0.86158497188772356f)   // a*c, a = 2 exactly
#define CONST_BASE (0.0f)

#define CANDSZ 512
#define SMALLN 64
#define SCW    134.7368421f    // 256 / 1.9   (window width 1.9 sigma)
#define OFC    323.3684211f    // 2.4 * 256 / 1.9

#define KW   32          // 32 b32 words per row (64 bf16)
#define SPAD 36          // padded row stride in words
#define GSMEM (4 * 128 * SPAD * 4)   // 73728 bytes dynamic smem for gemm

// ---------------- device scratch ----------------
__device__ __nv_bfloat16 g_innerB[(size_t)NPTS * NPTS];   // 32 MB
__device__ unsigned g_maskArr[NPTS];
__device__ unsigned g_Ybits[LLAB * (NPTS / 32)];
__device__ float2   g_rowout[NPTS];
__device__ unsigned g_ctr;
__device__ float    g_sigR[NPTS];    // sigma = |u_i|
__device__ float    g_sigI[NPTS];    // 1/sigma (0 if degenerate)
__device__ __align__(16) unsigned g_Uhi[NPTS * KW];
__device__ __align__(16) unsigned g_Ulo[NPTS * KW];
__device__ __align__(16) unsigned g_Vhi[NPTS * KW];
__device__ __align__(16) unsigned g_Vlo[NPTS * KW];

// ---------------- helpers ----------------
__device__ __forceinline__ unsigned fkey(float f) {
    unsigned u = __float_as_uint(f);
    return u ^ (((unsigned)((int)u >> 31)) | 0x80000000u);
}
__device__ __forceinline__ float finv(unsigned k) {
    unsigned u = (k & 0x80000000u) ? (k ^ 0x80000000u) : ~k;
    return __uint_as_float(u);
}

__device__ __forceinline__ float4 blockReduce4(float4 v, float4* sh) {
    int tid = threadIdx.x, lane = tid & 31, wid = tid >> 5;
    #pragma unroll
    for (int o = 16; o > 0; o >>= 1) {
        v.x += __shfl_down_sync(0xffffffffu, v.x, o);
        v.y += __shfl_down_sync(0xffffffffu, v.y, o);
        v.z += __shfl_down_sync(0xffffffffu, v.z, o);
        v.w += __shfl_down_sync(0xffffffffu, v.w, o);
    }
    if (lane == 0) sh[wid] = v;
    __syncthreads();
    float4 s = sh[0];
    #pragma unroll
    for (int w = 1; w < RT / 32; w++) {
        float4 t = sh[w];
        s.x += t.x; s.y += t.y; s.z += t.z; s.w += t.w;
    }
    __syncthreads();
    return s;
}

__device__ __forceinline__ unsigned pack_hi(float x0, float x1) {
    __nv_bfloat16 h0 = __float2bfloat16_rn(x0);
    __nv_bfloat16 h1 = __float2bfloat16_rn(x1);
    unsigned r0 = (unsigned)__nv_bfloat16_raw(h0).x;
    unsigned r1 = (unsigned)__nv_bfloat16_raw(h1).x;
    return r0 | (r1 << 16);
}
__device__ __forceinline__ unsigned pack_lo(float x0, float x1) {
    __nv_bfloat16 h0 = __float2bfloat16_rn(x0);
    __nv_bfloat16 h1 = __float2bfloat16_rn(x1);
    __nv_bfloat16 l0 = __float2bfloat16_rn(x0 - __bfloat162float(h0));
    __nv_bfloat16 l1 = __float2bfloat16_rn(x1 - __bfloat162float(h1));
    unsigned r0 = (unsigned)__nv_bfloat16_raw(l0).x;
    unsigned r1 = (unsigned)__nv_bfloat16_raw(l1).x;
    return r0 | (r1 << 16);
}

// ---------------- kernel 0: split-bf16 conversion + masks + row sigma ----------------
__global__ void __launch_bounds__(256) prep_kernel(const float* __restrict__ U,
                                                   const float* __restrict__ V,
                                                   const int* __restrict__ y) {
    int idx = blockIdx.x * 256 + threadIdx.x;     // NPTS*32 threads, one warp per U row
    int row = idx >> 5, w = idx & 31;
    float2 uu = *(const float2*)(U + (size_t)row * BITD + 2 * w);
    float2 vv = *(const float2*)(V + (size_t)row * BITD + 2 * w);
    g_Uhi[row * KW + w] = pack_hi(uu.x, uu.y);
    g_Ulo[row * KW + w] = pack_lo(uu.x, uu.y);
    g_Vhi[row * KW + w] = pack_hi(vv.x, vv.y);
    g_Vlo[row * KW + w] = pack_lo(vv.x, vv.y);

    float s2 = fmaf(uu.x, uu.x, uu.y * uu.y);
    #pragma unroll
    for (int o = 16; o > 0; o >>= 1) s2 += __shfl_down_sync(0xffffffffu, s2, o);
    if ((idx & 31) == 0) {
        float sg = sqrtf(s2);
        g_sigR[row] = sg;
        g_sigI[row] = (sg > 1e-20f) ? __frcp_rn(sg) : 0.f;
    }

    if (idx < NPTS) {
        int j = idx, lane = j & 31;
        unsigned m = 0;
        #pragma unroll
        for (int l = 0; l < LLAB; l++) m |= (y[j * LLAB + l] != 0 ? 1u : 0u) << l;
        g_maskArr[j] = m;
        int word = j >> 5;
        #pragma unroll
        for (int b = 0; b < LLAB; b++) {
            unsigned bal = __ballot_sync(0xffffffffu, (m >> b) & 1u);
            if (lane == 0) g_Ybits[b * (NPTS / 32) + word] = bal;
        }
        if (j == 0) g_ctr = 0;
    }
}

// ---------------- bf16 mma wrapper (m16n8k16, f32 accum) ----------------
__device__ __forceinline__ void mma_bf16(float& c0, float& c1, float& c2, float& c3,
                                         unsigned a0, unsigned a1, unsigned a2, unsigned a3,
                                         unsigned b0, unsigned b1) {
    asm volatile(
        "mma.sync.aligned.m16n8k16.row.col.f32.bf16.bf16.f32 "
        "{%0,%1,%2,%3}, {%4,%5,%6,%7}, {%8,%9}, {%0,%1,%2,%3};"
        : "+f"(c0), "+f"(c1), "+f"(c2), "+f"(c3)
        : "r"(a0), "r"(a1), "r"(a2), "r"(a3), "r"(b0), "r"(b1));
}

// ---------------- kernel 1: inner = U @ V^T, 128x128 tile, split-bf16 MMA ----------------
// 8 warps, warp tile 32 rows x 64 cols (2 row-atoms x 8 col-atoms).
__global__ void __launch_bounds__(256) gemm_kernel() {
    extern __shared__ unsigned smemU[];
    unsigned* sAhi = smemU;
    unsigned* sAlo = smemU + 128 * SPAD;
    unsigned* sBhi = smemU + 2 * 128 * SPAD;
    unsigned* sBlo = smemU + 3 * 128 * SPAD;

    int tid = threadIdx.x;
    int brow = blockIdx.y * 128, bcol = blockIdx.x * 128;

    // stage 128 rows x 32 words per array (1024 uint4 slots per array)
    #pragma unroll
    for (int it = 0; it < 4; it++) {
        int s = it * 256 + tid;            // 0..1023
        int r = s >> 3, j4 = (s & 7) * 4;
        size_t ga = (size_t)(brow + r) * KW + j4;
        size_t gb = (size_t)(bcol + r) * KW + j4;
        int w0 = r * SPAD + j4;
        *(uint4*)(&sAhi[w0]) = *(const uint4*)(&g_Uhi[ga]);
        *(uint4*)(&sAlo[w0]) = *(const uint4*)(&g_Ulo[ga]);
        *(uint4*)(&sBhi[w0]) = *(const uint4*)(&g_Vhi[gb]);
        *(uint4*)(&sBlo[w0]) = *(const uint4*)(&g_Vlo[gb]);
    }
    __syncthreads();

    int wpid = tid >> 5, lane = tid & 31;
    int warpRow = (wpid >> 1) * 32;        // 0,32,64,96
    int warpCol = (wpid & 1) * 64;         // 0,64
    int lr = lane >> 2, lc = lane & 3;

    float c[2][8][4];
    #pragma unroll
    for (int ra = 0; ra < 2; ra++)
        #pragma unroll
        for (int ca = 0; ca < 8; ca++)
            #pragma unroll
            for (int k = 0; k < 4; k++) c[ra][ca][k] = 0.f;

    #pragma unroll
    for (int kc = 0; kc < 4; kc++) {
        int aw = kc * 8 + lc;
        unsigned ah[2][4], al[2][4];
        #pragma unroll
        for (int ra = 0; ra < 2; ra++) {
            int base = warpRow + ra * 16;
            int ar0 = (base + lr) * SPAD, ar1 = (base + lr + 8) * SPAD;
            ah[ra][0] = sAhi[ar0 + aw];     ah[ra][1] = sAhi[ar1 + aw];
            ah[ra][2] = sAhi[ar0 + aw + 4]; ah[ra][3] = sAhi[ar1 + aw + 4];
            al[ra][0] = sAlo[ar0 + aw];     al[ra][1] = sAlo[ar1 + aw];
            al[ra][2] = sAlo[ar0 + aw + 4]; al[ra][3] = sAlo[ar1 + aw + 4];
        }
        #pragma unroll
        for (int ca = 0; ca < 8; ca++) {
            int bn = (warpCol + ca * 8 + lr) * SPAD;
            unsigned bh0 = sBhi[bn + aw], bh1 = sBhi[bn + aw + 4];
            unsigned bl0 = sBlo[bn + aw], bl1 = sBlo[bn + aw + 4];
            #pragma unroll
            for (int ra = 0; ra < 2; ra++) {
                mma_bf16(c[ra][ca][0], c[ra][ca][1], c[ra][ca][2], c[ra][ca][3],
                         ah[ra][0], ah[ra][1], ah[ra][2], ah[ra][3], bh0, bh1);
                mma_bf16(c[ra][ca][0], c[ra][ca][1], c[ra][ca][2], c[ra][ca][3],
                         ah[ra][0], ah[ra][1], ah[ra][2], ah[ra][3], bl0, bl1);
                mma_bf16(c[ra][ca][0], c[ra][ca][1], c[ra][ca][2], c[ra][ca][3],
                         al[ra][0], al[ra][1], al[ra][2], al[ra][3], bh0, bh1);
            }
        }
    }

    // store C as bf16
    #pragma unroll
    for (int ra = 0; ra < 2; ra++) {
        int r0 = brow + warpRow + ra * 16 + lr;
        #pragma unroll
        for (int ca = 0; ca < 8; ca++) {
            int col = bcol + warpCol + ca * 8 + 2 * lc;
            __nv_bfloat162 p0 = __float22bfloat162_rn(make_float2(c[ra][ca][0], c[ra][ca][1]));
            __nv_bfloat162 p1 = __float22bfloat162_rn(make_float2(c[ra][ca][2], c[ra][ca][3]));
            *(__nv_bfloat162*)(&g_innerB[(size_t)r0 * NPTS + col]) = p0;
            *(__nv_bfloat162*)(&g_innerB[(size_t)(r0 + 8) * NPTS + col]) = p1;
        }
    }
}

// ---------------- scan over packed 256-bin histogram, with totals ----------------
__device__ __forceinline__ void scan256(const unsigned* subH,
                                        unsigned rqS, unsigned rqD,
                                        unsigned* wsum, unsigned* brS, unsigned* brD,
                                        unsigned* totS, unsigned* totD) {
    int tid = threadIdx.x, lane = tid & 31, wid = tid >> 5;
    if (tid == 0) { brS[0] = 0u; brS[1] = 1u; brD[0] = 0u; brD[1] = 1u; }
    unsigned h = subH[tid];
    unsigned v = h;
    #pragma unroll
    for (int o = 1; o < 32; o <<= 1) {
        unsigned t = __shfl_up_sync(0xffffffffu, v, o);
        if (lane >= o) v += t;
    }
    if (lane == 31) wsum[wid] = v;
    __syncthreads();
    unsigned wb = 0, tot = 0;
    #pragma unroll
    for (int w = 0; w < RT / 32; w++) {
        unsigned t = wsum[w];
        if (w < wid) wb += t;
        tot += t;
    }
    unsigned incl = wb + v, excl = incl - h;
    unsigned inclS = incl & 0xFFFFu, exclS = excl & 0xFFFFu;
    unsigned inclD = incl >> 16,     exclD = excl >> 16;
    if (rqS > exclS && rqS <= inclS) { brS[0] = (unsigned)tid; brS[1] = rqS - exclS; }
    if (rqD > exclD && rqD <= inclD) { brD[0] = (unsigned)tid; brD[1] = rqD - exclD; }
    *totS = tot & 0xFFFFu;
    *totD = tot >> 16;
    __syncthreads();
}

// exact r-th smallest among c candidate keys (tie-aware counting select)
__device__ __forceinline__ void selectCount(const unsigned* cand, int c,
                                            unsigned r, unsigned* outT) {
    int tid = threadIdx.x;
    for (int idx = tid; idx < c; idx += RT) {
        unsigned mk = cand[idx];
        unsigned below = 0, eq = 0;
        for (int j = 0; j < c; j++) {
            unsigned k = cand[j];
            below += (k < mk); eq += (k == mk);
        }
        if (below < r && r <= below + eq) outT[0] = mk;
    }
    __syncthreads();
}

// ---------------- kernel 2: per-row loss (+ fused final reduction) ----------------
__global__ void __launch_bounds__(RT, 5) row_kernel(float* __restrict__ out) {
    __shared__ unsigned candS[CANDSZ], candD[CANDSZ];
    __shared__ unsigned subH[256];
    __shared__ unsigned wshA[RT / 32], wshB[RT / 32];
    __shared__ float4   fsh4[RT / 32];
    __shared__ unsigned brS[2], brD[2];
    __shared__ unsigned ccS, ccD, TkS, TkD;
    __shared__ int      lastFlag;

    int tid = threadIdx.x, lane = tid & 31, wid = tid >> 5;
    int i = blockIdx.x;

    subH[tid] = 0u;

    unsigned mi = g_maskArr[i];
    unsigned cls = 0;
    const unsigned short* yb = (const unsigned short*)g_Ybits;
    #pragma unroll
    for (int b = 0; b < LLAB; b++) {
        unsigned w = (unsigned)yb[b * (NPTS / 16) + tid];
        cls |= w & (0u - ((mi >> b) & 1u));
    }
    float sig  = g_sigR[i];
    float scS  = SCW * g_sigI[i];    // 0 when degenerate -> t = OFC >= 256 -> no bin

    // load 16 bf16 values, expand to f32
    const uint4* rp = (const uint4*)(g_innerB + (size_t)i * NPTS + tid * 16);
    uint4 p0 = __ldcs(rp);
    uint4 p1 = __ldcs(rp + 1);
    float xv[16];
    {
        unsigned wds[8] = {p0.x, p0.y, p0.z, p0.w, p1.x, p1.y, p1.z, p1.w};
        #pragma unroll
        for (int q = 0; q < 8; q++) {
            __nv_bfloat162 h = *(__nv_bfloat162*)&wds[q];
            float2 f = __bfloat1622float2(h);
            xv[q * 2 + 0] = f.x;
            xv[q * 2 + 1] = f.y;
        }
    }
    __syncthreads();   // subH cleared

    // merged pass: class sums + popcount + windowed histogram + below-window counts
    float sAll = 0.f, sS = 0.f;
    unsigned cb = 0;
    #pragma unroll
    for (int e = 0; e < 16; e++) {
        float x = xv[e];
        bool isS = (cls >> e) & 1u;
        sAll += x;
        if (isS) sS += x;
        float t = fmaf(isS ? x : -x, scS, OFC);   // S: [-2.4s,-0.5s]; D: [0.5s,2.4s]
        unsigned inc = isS ? 1u : 0x10000u;
        if (t < 0.f) cb += inc;
        else if (t < 256.0f) atomicAdd(&subH[(int)t], inc);
    }
    {
        #pragma unroll
        for (int o = 16; o > 0; o >>= 1) {
            sAll += __shfl_down_sync(0xffffffffu, sAll, o);
            sS   += __shfl_down_sync(0xffffffffu, sS, o);
        }
        unsigned pcw = __reduce_add_sync(0xffffffffu, __popc(cls));
        unsigned cbw = __reduce_add_sync(0xffffffffu, cb);
        if (lane == 0) {
            fsh4[wid] = make_float4(sAll, sS, 0.f, 0.f);
            wshA[wid] = pcw; wshB[wid] = cbw;
        }
    }
    __syncthreads();
    unsigned pc, cbt;
    {
        float4 fa = fsh4[0]; unsigned pct = wshA[0], cbx = wshB[0];
        #pragma unroll
        for (int w = 1; w < RT / 32; w++) {
            float4 ft = fsh4[w];
            fa.x += ft.x; fa.y += ft.y;
            pct += wshA[w]; cbx += wshB[w];
        }
        sAll = fa.x; sS = fa.y; pc = pct; cbt = cbx;
    }
    __syncthreads();

    int ns = (int)pc, nd = NPTS - ns;
    float sD = sAll - sS;
    int ksr = (ns * 9) / 10, kdr = (nd * 9) / 10;
    unsigned qS = (unsigned)(ns - ksr), qD = (unsigned)(nd - kdr);
    bool valid = (ns > 0) && (nd > 0);

    float rowres = 0.f;
    if (valid) {
        float muS = sS / (float)ns;
        float muD = sD / (float)nd;
        bool bigS = ns > SMALLN, bigD = nd > SMALLN;
        unsigned cbS = cbt & 0xFFFFu, cbD = cbt >> 16;

        unsigned totS, totD;
        scan256(subH, (bigS && qS > cbS) ? (qS - cbS) : 0u,
                      (bigD && qD > cbD) ? (qD - cbD) : 0u,
                wshA, brS, brD, &totS, &totD);
        bool okS = !bigS || ((qS > cbS) && (qS - cbS) <= totS);
        bool okD = !bigD || ((qD > cbD) && (qD - cbD) <= totD);
        unsigned binS = brS[0], binD = brD[0];
        unsigned rkS = (bigS && okS) ? brS[1] : qS;
        unsigned rkD = (bigD && okD) ? brD[1] : qD;
        float fscS = scS, fofS = OFC;
        float fscD = -scS, fofD = OFC;

        // attempt 2 (rare): exact class means, Chebyshev-safe +/-20 sigma window
        if ((bigS && !okS) || (bigD && !okD)) {
            bool aS = bigS && !okS, aD = bigD && !okD;
            float w2 = 40.f * sig;
            float sc2 = (w2 > 1e-30f) ? 256.f / w2 : 0.f;
            bool dg = (sc2 == 0.f);
            float of2S = -(muS - 20.f * sig) * sc2;
            float of2D = (muD + 20.f * sig) * sc2;
            subH[tid] = 0u;
            __syncthreads();
            unsigned cb2 = 0;
            #pragma unroll
            for (int e = 0; e < 16; e++) {
                float x = xv[e];
                bool isS = (cls >> e) & 1u;
                bool act = (isS ? aS : aD) && !dg;
                float t = fmaf(isS ? x : -x, sc2, isS ? of2S : of2D);
                unsigned inc = isS ? 1u : 0x10000u;
                if (act) {
                    if (t < 0.f) cb2 += inc;
                    else if (t < 256.0f) atomicAdd(&subH[(int)t], inc);
                }
            }
            cb2 = __reduce_add_sync(0xffffffffu, cb2);
            if (lane == 0) wshB[wid] = cb2;
            __syncthreads();
            unsigned c2t = 0;
            #pragma unroll
            for (int w = 0; w < RT / 32; w++) c2t += wshB[w];
            unsigned c2S = c2t & 0xFFFFu, c2D = c2t >> 16;
            unsigned t2S, t2D;
            scan256(subH, (aS && !dg && qS > c2S) ? (qS - c2S) : 0u,
                          (aD && !dg && qD > c2D) ? (qD - c2D) : 0u,
                    wshA, brS, brD, &t2S, &t2D);
            if (aS) {
                if (!dg && (qS > c2S) && (qS - c2S) <= t2S) {
                    binS = brS[0]; rkS = brS[1]; fscS = sc2; fofS = of2S;
                } else { fscS = 0.f; fofS = -1.f; }
            }
            if (aD) {
                if (!dg && (qD > c2D) && (qD - c2D) <= t2D) {
                    binD = brD[0]; rkD = brD[1]; fscD = -sc2; fofD = of2D;
                } else { fscD = 0.f; fofD = -1.f; }
            }
        }

        // compact candidates of located bins (small class: all elements)
        if (tid == 0) { ccS = 0u; ccD = 0u; TkS = fkey(muS); TkD = ~fkey(muD); }
        __syncthreads();
        #pragma unroll
        for (int e = 0; e < 16; e++) {
            float x = xv[e];
            bool isS = (cls >> e) & 1u;
            bool big = isS ? bigS : bigD;
            float t = fmaf(x, isS ? fscS : fscD, isS ? fofS : fofD);
            unsigned bsel = isS ? binS : binD;
            bool put = !big || (t >= 0.f && t < 256.0f && (unsigned)(int)t == bsel);
            if (put) {
                if (isS) {
                    unsigned idx = atomicAdd(&ccS, 1u);
                    if (idx < CANDSZ) candS[idx] = fkey(x);
                } else {
                    unsigned idx = atomicAdd(&ccD, 1u);
                    if (idx < CANDSZ) candD[idx] = ~fkey(x);
                }
            }
        }
        __syncthreads();
        selectCount(candS, (int)min(ccS, (unsigned)CANDSZ), rkS, &TkS);
        selectCount(candD, (int)min(ccD, (unsigned)CANDSZ), rkD, &TkD);
        float tsF = finv(TkS);
        float tdF = finv(~TkD);

        float sLS = 0.f, sLD = 0.f, cLS = 0.f, cLD = 0.f;
        #pragma unroll
        for (int e = 0; e < 16; e++) {
            float x = xv[e];
            bool isS = (cls >> e) & 1u;
            bool hit = isS ? (x < tsF) : (x > tdF);
            if (hit) {
                if (isS) { sLS += x; cLS += 1.f; }
                else     { sLD += x; cLD += 1.f; }
            }
        }
        float4 r1 = blockReduce4(make_float4(sLS, sLD, cLS, cLD), fsh4);
        float simMinSum = r1.x + ((float)qS - r1.z) * tsF;
        float disMaxSum = r1.y + ((float)qD - r1.w) * tdF;

        float similarMin    = simMinSum / (float)max((int)qS, 1);
        float dissimilarMax = disMaxSum / (float)max((int)qD, 1);
        float meanS  = fminf(fmaxf(muS, 0.f), UPPERB);
        float meanDS = fminf(fmaxf(muD, 0.f), UPPERB);

        float BP   = meanS  - (UPPERB - meanS) / UPPERB * fabsf(meanS - dissimilarMax);
        float BPds = meanDS - meanDS / UPPERB * fabsf(meanDS - similarMin);

        // softplus pass (ac = 2c): f = C*(z+min(z,0))
        float pos = 0.f, nav = 0.f;
        #pragma unroll
        for (int e = 0; e < 16; e++) {
            float x = xv[e];
            bool isS = (cls >> e) & 1u;
            float z = isS ? (x - BP) : (BPds - x);
            float zz = z + fminf(z, 0.f);
            float f = CONST_C * zz;
            float sp = fmaxf(f, 0.f) + __logf(1.f + __expf(-fabsf(f)));
            if (isS) pos += sp; else nav += sp;
        }
        float4 r2 = blockReduce4(make_float4(pos, nav, 0.f, 0.f), fsh4);
        rowres = r2.x / (float)max(ns, 1) + r2.y / (float)max(nd, 1);
    }

    if (tid == 0) {
        g_rowout[i] = make_float2(valid ? rowres : 0.f, valid ? 1.f : 0.f);
        __threadfence();
        unsigned old = atomicAdd(&g_ctr, 1u);
        lastFlag = (old == NPTS - 1) ? 1 : 0;
    }
    __syncthreads();

    if (lastFlag) {
        __threadfence();
        float t = 0.f, c = 0.f;
        for (int idx = tid; idx < NPTS; idx += RT) {
            float2 rv = g_rowout[idx];
            t += rv.x; c += rv.y;
        }
        float4 r3 = blockReduce4(make_float4(t, c, 0.f, 0.f), fsh4);
        if (tid == 0) out[0] = (r3.y > 0.f) ? r3.x / fmaxf(r3.y, 1.f) : 0.f;
    }
}

// ---------------- launch ----------------
extern "C" void kernel_launch(void* const* d_in, const int* in_sizes, int n_in,
                              void* d_out, int out_size) {
    const float* u = (const float*)d_in[0];
    const float* v = (const float*)d_in[1];
    const int*   y = (const int*)d_in[2];

    cudaFuncSetAttribute(gemm_kernel, cudaFuncAttributeMaxDynamicSharedMemorySize, GSMEM);

    prep_kernel<<<(NPTS * KW) / 256, 256>>>(u, v, y);
    dim3 gg(NPTS / 128, NPTS / 128);
    gemm_kernel<<<gg, 256, GSMEM>>>();
    row_kernel<<<NPTS, RT>>>((float*)d_out);
}

// round 16
// speedup vs baseline: 1.5311x; 1.2595x over previous
#include <cuda_runtime.h>
#include <cuda_bf16.h>
#include <math.h>

#define NPTS 4096
#define BITD 64
#define LLAB 10
#define RT   256
#define UPPERB 16.0f
// c = (1/right)*ln(yp/(99(1-yp))) with right=64/6, yp=0.5  -> -6*ln(99)/64
#define CONST_C    (-0.43079248594386178f)

#define KW   32          // 32 b32 words per row (64 bf16)
#define SPAD 36          // padded row stride in words
#define GSMEM (4 * 128 * SPAD * 4)   // 73728 bytes dynamic smem for gemm

// ---------------- device scratch ----------------
__device__ __nv_bfloat16 g_innerB[(size_t)NPTS * NPTS];   // 32 MB
__device__ unsigned g_maskArr[NPTS];
__device__ unsigned g_Ybits[LLAB * (NPTS / 32)];
__device__ float2   g_rowout[NPTS];
__device__ unsigned g_ctr;
__device__ float    g_sigR[NPTS];    // sigma = |u_i|
__device__ float    g_sigI[NPTS];    // 1/sigma (0 if degenerate)
__device__ __align__(16) unsigned g_Uhi[NPTS * KW];
__device__ __align__(16) unsigned g_Ulo[NPTS * KW];
__device__ __align__(16) unsigned g_Vhi[NPTS * KW];
__device__ __align__(16) unsigned g_Vlo[NPTS * KW];

// ---------------- helpers ----------------
__device__ __forceinline__ unsigned fkey(float f) {
    unsigned u = __float_as_uint(f);
    return u ^ (((unsigned)((int)u >> 31)) | 0x80000000u);
}
__device__ __forceinline__ float finv(unsigned k) {
    unsigned u = (k & 0x80000000u) ? (k ^ 0x80000000u) : ~k;
    return __uint_as_float(u);
}

__device__ __forceinline__ float4 blockReduce4(float4 v, float4* sh) {
    int tid = threadIdx.x, lane = tid & 31, wid = tid >> 5;
    #pragma unroll
    for (int o = 16; o > 0; o >>= 1) {
        v.x += __shfl_down_sync(0xffffffffu, v.x, o);
        v.y += __shfl_down_sync(0xffffffffu, v.y, o);
        v.z += __shfl_down_sync(0xffffffffu, v.z, o);
        v.w += __shfl_down_sync(0xffffffffu, v.w, o);
    }
    if (lane == 0) sh[wid] = v;
    __syncthreads();
    float4 s = sh[0];
    #pragma unroll
    for (int w = 1; w < RT / 32; w++) {
        float4 t = sh[w];
        s.x += t.x; s.y += t.y; s.z += t.z; s.w += t.w;
    }
    __syncthreads();
    return s;
}

__device__ __forceinline__ unsigned pack_hi(float x0, float x1) {
    __nv_bfloat16 h0 = __float2bfloat16_rn(x0);
    __nv_bfloat16 h1 = __float2bfloat16_rn(x1);
    return (unsigned)__nv_bfloat16_raw(h0).x | ((unsigned)__nv_bfloat16_raw(h1).x << 16);
}
__device__ __forceinline__ unsigned pack_lo(float x0, float x1) {
    __nv_bfloat16 h0 = __float2bfloat16_rn(x0);
    __nv_bfloat16 h1 = __float2bfloat16_rn(x1);
    __nv_bfloat16 l0 = __float2bfloat16_rn(x0 - __bfloat162float(h0));
    __nv_bfloat16 l1 = __float2bfloat16_rn(x1 - __bfloat162float(h1));
    return (unsigned)__nv_bfloat16_raw(l0).x | ((unsigned)__nv_bfloat16_raw(l1).x << 16);
}

// ---------------- kernel 0: split-bf16 conversion + masks + row sigma ----------------
__global__ void __launch_bounds__(256) prep_kernel(const float* __restrict__ U,
                                                   const float* __restrict__ V,
                                                   const int* __restrict__ y) {
    int idx = blockIdx.x * 256 + threadIdx.x;
    int row = idx >> 5, w = idx & 31;
    float2 uu = *(const float2*)(U + (size_t)row * BITD + 2 * w);
    float2 vv = *(const float2*)(V + (size_t)row * BITD + 2 * w);
    g_Uhi[row * KW + w] = pack_hi(uu.x, uu.y);
    g_Ulo[row * KW + w] = pack_lo(uu.x, uu.y);
    g_Vhi[row * KW + w] = pack_hi(vv.x, vv.y);
    g_Vlo[row * KW + w] = pack_lo(vv.x, vv.y);

    float s2 = fmaf(uu.x, uu.x, uu.y * uu.y);
    #pragma unroll
    for (int o = 16; o > 0; o >>= 1) s2 += __shfl_down_sync(0xffffffffu, s2, o);
    if ((idx & 31) == 0) {
        float sg = sqrtf(s2);
        g_sigR[row] = sg;
        g_sigI[row] = (sg > 1e-20f) ? __frcp_rn(sg) : 0.f;
    }

    if (idx < NPTS) {
        int j = idx, lane = j & 31;
        unsigned m = 0;
        #pragma unroll
        for (int l = 0; l < LLAB; l++) m |= (y[j * LLAB + l] != 0 ? 1u : 0u) << l;
        g_maskArr[j] = m;
        int word = j >> 5;
        #pragma unroll
        for (int b = 0; b < LLAB; b++) {
            unsigned bal = __ballot_sync(0xffffffffu, (m >> b) & 1u);
            if (lane == 0) g_Ybits[b * (NPTS / 32) + word] = bal;
        }
        if (j == 0) g_ctr = 0;
    }
}

// ---------------- bf16 mma wrapper (m16n8k16, f32 accum) ----------------
__device__ __forceinline__ void mma_bf16(float& c0, float& c1, float& c2, float& c3,
                                         unsigned a0, unsigned a1, unsigned a2, unsigned a3,
                                         unsigned b0, unsigned b1) {
    asm volatile(
        "mma.sync.aligned.m16n8k16.row.col.f32.bf16.bf16.f32 "
        "{%0,%1,%2,%3}, {%4,%5,%6,%7}, {%8,%9}, {%0,%1,%2,%3};"
        : "+f"(c0), "+f"(c1), "+f"(c2), "+f"(c3)
        : "r"(a0), "r"(a1), "r"(a2), "r"(a3), "r"(b0), "r"(b1));
}

// ---------------- kernel 1: inner = U @ V^T, 128x128 tile, split-bf16 MMA ----------------
__global__ void __launch_bounds__(256) gemm_kernel() {
    extern __shared__ unsigned smemU[];
    unsigned* sAhi = smemU;
    unsigned* sAlo = smemU + 128 * SPAD;
    unsigned* sBhi = smemU + 2 * 128 * SPAD;
    unsigned* sBlo = smemU + 3 * 128 * SPAD;

    int tid = threadIdx.x;
    int brow = blockIdx.y * 128, bcol = blockIdx.x * 128;

    #pragma unroll
    for (int it = 0; it < 4; it++) {
        int s = it * 256 + tid;
        int r = s >> 3, j4 = (s & 7) * 4;
        size_t ga = (size_t)(brow + r) * KW + j4;
        size_t gb = (size_t)(bcol + r) * KW + j4;
        int w0 = r * SPAD + j4;
        *(uint4*)(&sAhi[w0]) = *(const uint4*)(&g_Uhi[ga]);
        *(uint4*)(&sAlo[w0]) = *(const uint4*)(&g_Ulo[ga]);
        *(uint4*)(&sBhi[w0]) = *(const uint4*)(&g_Vhi[gb]);
        *(uint4*)(&sBlo[w0]) = *(const uint4*)(&g_Vlo[gb]);
    }
    __syncthreads();

    int wpid = tid >> 5, lane = tid & 31;
    int warpRow = (wpid >> 1) * 32;
    int warpCol = (wpid & 1) * 64;
    int lr = lane >> 2, lc = lane & 3;

    float c[2][8][4];
    #pragma unroll
    for (int ra = 0; ra < 2; ra++)
        #pragma unroll
        for (int ca = 0; ca < 8; ca++)
            #pragma unroll
            for (int k = 0; k < 4; k++) c[ra][ca][k] = 0.f;

    #pragma unroll
    for (int kc = 0; kc < 4; kc++) {
        int aw = kc * 8 + lc;
        unsigned ah[2][4], al[2][4];
        #pragma unroll
        for (int ra = 0; ra < 2; ra++) {
            int base = warpRow + ra * 16;
            int ar0 = (base + lr) * SPAD, ar1 = (base + lr + 8) * SPAD;
            ah[ra][0] = sAhi[ar0 + aw];     ah[ra][1] = sAhi[ar1 + aw];
            ah[ra][2] = sAhi[ar0 + aw + 4]; ah[ra][3] = sAhi[ar1 + aw + 4];
            al[ra][0] = sAlo[ar0 + aw];     al[ra][1] = sAlo[ar1 + aw];
            al[ra][2] = sAlo[ar0 + aw + 4]; al[ra][3] = sAlo[ar1 + aw + 4];
        }
        #pragma unroll
        for (int ca = 0; ca < 8; ca++) {
            int bn = (warpCol + ca * 8 + lr) * SPAD;
            unsigned bh0 = sBhi[bn + aw], bh1 = sBhi[bn + aw + 4];
            unsigned bl0 = sBlo[bn + aw], bl1 = sBlo[bn + aw + 4];
            #pragma unroll
            for (int ra = 0; ra < 2; ra++) {
                mma_bf16(c[ra][ca][0], c[ra][ca][1], c[ra][ca][2], c[ra][ca][3],
                         ah[ra][0], ah[ra][1], ah[ra][2], ah[ra][3], bh0, bh1);
                mma_bf16(c[ra][ca][0], c[ra][ca][1], c[ra][ca][2], c[ra][ca][3],
                         ah[ra][0], ah[ra][1], ah[ra][2], ah[ra][3], bl0, bl1);
                mma_bf16(c[ra][ca][0], c[ra][ca][1], c[ra][ca][2], c[ra][ca][3],
                         al[ra][0], al[ra][1], al[ra][2], al[ra][3], bh0, bh1);
            }
        }
    }

    #pragma unroll
    for (int ra = 0; ra < 2; ra++) {
        int r0 = brow + warpRow + ra * 16 + lr;
        #pragma unroll
        for (int ca = 0; ca < 8; ca++) {
            int col = bcol + warpCol + ca * 8 + 2 * lc;
            __nv_bfloat162 p0 = __float22bfloat162_rn(make_float2(c[ra][ca][0], c[ra][ca][1]));
            __nv_bfloat162 p1 = __float22bfloat162_rn(make_float2(c[ra][ca][2], c[ra][ca][3]));
            *(__nv_bfloat162*)(&g_innerB[(size_t)r0 * NPTS + col]) = p0;
            *(__nv_bfloat162*)(&g_innerB[(size_t)(r0 + 8) * NPTS + col]) = p1;
        }
    }
}

// ---------------- scan over packed 512-bin histogram (2 bins/thread) ----------------
// brX[0] = bin (sentinel 0xFFFFFFFF if rank not found / rq==0), brX[1] = rank in bin.
__device__ __forceinline__ void scan512(const unsigned* hist,
                                        unsigned rqS, unsigned rqD,
                                        unsigned* wsum, unsigned* brS, unsigned* brD) {
    int tid = threadIdx.x, lane = tid & 31, wid = tid >> 5;
    if (tid == 0) { brS[0] = 0xFFFFFFFFu; brD[0] = 0xFFFFFFFFu; brS[1] = 1u; brD[1] = 1u; }
    unsigned h0 = hist[2 * tid], h1 = hist[2 * tid + 1];
    unsigned s = h0 + h1;
    unsigned v = s;
    #pragma unroll
    for (int o = 1; o < 32; o <<= 1) {
        unsigned t = __shfl_up_sync(0xffffffffu, v, o);
        if (lane >= o) v += t;
    }
    if (lane == 31) wsum[wid] = v;
    __syncthreads();
    unsigned wb = 0;
    #pragma unroll
    for (int w = 0; w < RT / 32; w++) if (w < wid) wb += wsum[w];
    unsigned excl = wb + v - s;
    unsigned e0S = excl & 0xFFFFu, h0S = h0 & 0xFFFFu, h1S = h1 & 0xFFFFu;
    unsigned e0D = excl >> 16,     h0D = h0 >> 16,     h1D = h1 >> 16;
    if (rqS > e0S && rqS <= e0S + h0S) { brS[0] = 2u * tid; brS[1] = rqS - e0S; }
    else if (rqS > e0S + h0S && rqS <= e0S + h0S + h1S) { brS[0] = 2u * tid + 1u; brS[1] = rqS - e0S - h0S; }
    if (rqD > e0D && rqD <= e0D + h0D) { brD[0] = 2u * tid; brD[1] = rqD - e0D; }
    else if (rqD > e0D + h0D && rqD <= e0D + h0D + h1D) { brD[0] = 2u * tid + 1u; brD[1] = rqD - e0D - h0D; }
    __syncthreads();
}

// ---------------- scan over packed 256-bin histogram (1 bin/thread) ----------------
__device__ __forceinline__ void scan256(const unsigned* hist,
                                        unsigned rqS, unsigned rqD,
                                        unsigned* wsum, unsigned* brS, unsigned* brD) {
    int tid = threadIdx.x, lane = tid & 31, wid = tid >> 5;
    if (tid == 0) { brS[0] = 0xFFFFFFFFu; brD[0] = 0xFFFFFFFFu; brS[1] = 1u; brD[1] = 1u; }
    unsigned h = hist[tid];
    unsigned v = h;
    #pragma unroll
    for (int o = 1; o < 32; o <<= 1) {
        unsigned t = __shfl_up_sync(0xffffffffu, v, o);
        if (lane >= o) v += t;
    }
    if (lane == 31) wsum[wid] = v;
    __syncthreads();
    unsigned wb = 0;
    #pragma unroll
    for (int w = 0; w < RT / 32; w++) if (w < wid) wb += wsum[w];
    unsigned incl = wb + v, excl = incl - h;
    unsigned inclS = incl & 0xFFFFu, exclS = excl & 0xFFFFu;
    unsigned inclD = incl >> 16,     exclD = excl >> 16;
    if (rqS > exclS && rqS <= inclS) { brS[0] = (unsigned)tid; brS[1] = rqS - exclS; }
    if (rqD > exclD && rqD <= inclD) { brD[0] = (unsigned)tid; brD[1] = rqD - exclD; }
    __syncthreads();
}

// ---------------- kernel 2: per-row loss (+ fused final reduction) ----------------
__global__ void __launch_bounds__(RT, 5) row_kernel(float* __restrict__ out) {
    __shared__ unsigned hist[512];     // packed S|D exact-bf16-key counts
    __shared__ unsigned wshA[RT / 32], wshB[RT / 32];
    __shared__ float4   fsh4[RT / 32];
    __shared__ unsigned brS[2], brD[2];
    __shared__ int      lastFlag;

    int tid = threadIdx.x, lane = tid & 31, wid = tid >> 5;
    int i = blockIdx.x;

    hist[tid] = 0u; hist[tid + 256] = 0u;

    unsigned mi = g_maskArr[i];
    unsigned cls = 0;
    const unsigned short* yb = (const unsigned short*)g_Ybits;
    #pragma unroll
    for (int b = 0; b < LLAB; b++) {
        unsigned w = (unsigned)yb[b * (NPTS / 16) + tid];
        cls |= w & (0u - ((mi >> b) & 1u));
    }
    float sig = g_sigR[i];

    // window keys: S in [-2.4s, -0.5s), D (flipped keys) in (0.5s, 2.4s]
    float s24 = 2.4f * sig, s05 = 0.5f * sig;
    unsigned kLoS = fkey(-s24) >> 16, kHiS = fkey(-s05) >> 16;
    unsigned kLoD = (~fkey(s24)) >> 16, kHiD = (~fkey(s05)) >> 16;
    bool winOK = (sig > 1e-20f) && (kHiS - kLoS < 512u) && (kHiD - kLoD < 512u);
    if (!winOK) { kLoS = 0u; kHiS = 0u; kLoD = 0u; kHiD = 0u; }

    // load 16 bf16 values, expand to f32
    const uint4* rp = (const uint4*)(g_innerB + (size_t)i * NPTS + tid * 16);
    uint4 p0 = __ldcs(rp);
    uint4 p1 = __ldcs(rp + 1);
    float xv[16];
    {
        unsigned wds[8] = {p0.x, p0.y, p0.z, p0.w, p1.x, p1.y, p1.z, p1.w};
        #pragma unroll
        for (int q = 0; q < 8; q++) {
            __nv_bfloat162 h = *(__nv_bfloat162*)&wds[q];
            float2 f = __bfloat1622float2(h);
            xv[q * 2 + 0] = f.x;
            xv[q * 2 + 1] = f.y;
        }
    }
    __syncthreads();   // hist cleared

    // merged pass: sums + popcount + exact-key window histogram + below-window sums
    float sAll = 0.f, sS = 0.f, sbS = 0.f, sbD = 0.f;
    unsigned cb = 0;
    #pragma unroll
    for (int e = 0; e < 16; e++) {
        float x = xv[e];
        bool isS = (cls >> e) & 1u;
        sAll += x;
        if (isS) sS += x;
        unsigned k32 = fkey(x);
        unsigned k16 = isS ? (k32 >> 16) : ((~k32) >> 16);
        unsigned lo = isS ? kLoS : kLoD, hi = isS ? kHiS : kHiD;
        unsigned inc = isS ? 1u : 0x10000u;
        if (k16 < lo) { cb += inc; if (isS) sbS += x; else sbD += x; }
        else if (k16 < hi) atomicAdd(&hist[k16 - lo], inc);
    }
    {
        float4 v = make_float4(sAll, sS, sbS, sbD);
        #pragma unroll
        for (int o = 16; o > 0; o >>= 1) {
            v.x += __shfl_down_sync(0xffffffffu, v.x, o);
            v.y += __shfl_down_sync(0xffffffffu, v.y, o);
            v.z += __shfl_down_sync(0xffffffffu, v.z, o);
            v.w += __shfl_down_sync(0xffffffffu, v.w, o);
        }
        unsigned pcw = __reduce_add_sync(0xffffffffu, __popc(cls));
        unsigned cbw = __reduce_add_sync(0xffffffffu, cb);
        if (lane == 0) {
            fsh4[wid] = v;
            wshA[wid] = pcw; wshB[wid] = cbw;
        }
    }
    __syncthreads();
    unsigned pc, cbt;
    {
        float4 fa = fsh4[0]; unsigned pct = wshA[0], cbx = wshB[0];
        #pragma unroll
        for (int w = 1; w < RT / 32; w++) {
            float4 ft = fsh4[w];
            fa.x += ft.x; fa.y += ft.y; fa.z += ft.z; fa.w += ft.w;
            pct += wshA[w]; cbx += wshB[w];
        }
        sAll = fa.x; sS = fa.y; sbS = fa.z; sbD = fa.w; pc = pct; cbt = cbx;
    }
    __syncthreads();

    int ns = (int)pc, nd = NPTS - ns;
    float sD = sAll - sS;
    int ksr = (ns * 9) / 10, kdr = (nd * 9) / 10;
    unsigned qS = (unsigned)(ns - ksr), qD = (unsigned)(nd - kdr);
    bool valid = (ns > 0) && (nd > 0);

    float rowres = 0.f;
    if (valid) {
        float muS = sS / (float)ns;
        float muD = sD / (float)nd;
        unsigned cbS = cbt & 0xFFFFu, cbD = cbt >> 16;
        unsigned rqS = (winOK && qS > cbS) ? (qS - cbS) : 0u;
        unsigned rqD = (winOK && qD > cbD) ? (qD - cbD) : 0u;

        scan512(hist, rqS, rqD, wshA, brS, brD);
        unsigned binS = brS[0], rkS = brS[1];
        unsigned binD = brD[0], rkD = brD[1];
        bool okS = binS != 0xFFFFFFFFu, okD = binD != 0xFFFFFFFFu;

        // weighted sums of bins strictly below the selected bin (exact values)
        float wS = 0.f, wD = 0.f;
        #pragma unroll
        for (int q = 0; q < 2; q++) {
            unsigned b = 2u * tid + q;
            unsigned hh = hist[b];
            if (okS && b < binS) {
                unsigned c = hh & 0xFFFFu;
                if (c) wS += (float)c * finv((kLoS + b) << 16);
            }
            if (okD && b < binD) {
                unsigned c = hh >> 16;
                if (c) wD += (float)c * finv((~(kLoD + b)) << 16);
            }
        }
        float4 rw = blockReduce4(make_float4(wS, wD, 0.f, 0.f), fsh4);
        float tsF = okS ? finv((kLoS + binS) << 16) : 0.f;
        float tdF = okD ? finv((~(kLoD + binD)) << 16) : 0.f;
        float lowS = sbS + rw.x, lowD = sbD + rw.y;
        float tieS = (float)rkS, tieD = (float)rkD;

        if (!okS || !okD) {    // rare exact fallback: 8+8-bit radix on key16
            bool fbS = !okS, fbD = !okD;
            hist[tid] = 0u; hist[tid + 256] = 0u;
            __syncthreads();
            #pragma unroll
            for (int e = 0; e < 16; e++) {
                bool isS = (cls >> e) & 1u;
                if (isS ? fbS : fbD) {
                    unsigned k32 = fkey(xv[e]);
                    unsigned k16 = isS ? (k32 >> 16) : ((~k32) >> 16);
                    atomicAdd(&hist[k16 >> 8], isS ? 1u : 0x10000u);
                }
            }
            __syncthreads();
            scan256(hist, fbS ? qS : 0u, fbD ? qD : 0u, wshA, brS, brD);
            unsigned hbS = brS[0], r2S = brS[1];
            unsigned hbD = brD[0], r2D = brD[1];
            hist[tid] = 0u; hist[tid + 256] = 0u;
            __syncthreads();
            #pragma unroll
            for (int e = 0; e < 16; e++) {
                bool isS = (cls >> e) & 1u;
                if (isS ? fbS : fbD) {
                    unsigned k32 = fkey(xv[e]);
                    unsigned k16 = isS ? (k32 >> 16) : ((~k32) >> 16);
                    if ((k16 >> 8) == (isS ? hbS : hbD))
                        atomicAdd(&hist[k16 & 255u], isS ? 1u : 0x10000u);
                }
            }
            __syncthreads();
            scan256(hist, fbS ? r2S : 0u, fbD ? r2D : 0u, wshA, brS, brD);
            unsigned T16S = (hbS << 8) | brS[0];
            unsigned T16D = (hbD << 8) | brD[0];
            unsigned r3S = brS[1], r3D = brD[1];
            float sb2S = 0.f, sb2D = 0.f;
            #pragma unroll
            for (int e = 0; e < 16; e++) {
                bool isS = (cls >> e) & 1u;
                if (isS ? fbS : fbD) {
                    float x = xv[e];
                    unsigned k32 = fkey(x);
                    unsigned k16 = isS ? (k32 >> 16) : ((~k32) >> 16);
                    if (k16 < (isS ? T16S : T16D)) { if (isS) sb2S += x; else sb2D += x; }
                }
            }
            float4 r2 = blockReduce4(make_float4(sb2S, sb2D, 0.f, 0.f), fsh4);
            if (fbS) { tsF = finv(T16S << 16); lowS = r2.x; tieS = (float)r3S; }
            if (fbD) { tdF = finv((~T16D) << 16); lowD = r2.y; tieD = (float)r3D; }
        }

        float simMinSum = lowS + tieS * tsF;
        float disMaxSum = lowD + tieD * tdF;

        float similarMin    = simMinSum / (float)max((int)qS, 1);
        float dissimilarMax = disMaxSum / (float)max((int)qD, 1);
        float meanS  = fminf(fmaxf(muS, 0.f), UPPERB);
        float meanDS = fminf(fmaxf(muD, 0.f), UPPERB);

        float BP   = meanS  - (UPPERB - meanS) / UPPERB * fabsf(meanS - dissimilarMax);
        float BPds = meanDS - meanDS / UPPERB * fabsf(meanDS - similarMin);

        // softplus pass (ac = 2c): f = C*(z+min(z,0))
        float pos = 0.f, nav = 0.f;
        #pragma unroll
        for (int e = 0; e < 16; e++) {
            float x = xv[e];
            bool isS = (cls >> e) & 1u;
            float z = isS ? (x - BP) : (BPds - x);
            float zz = z + fminf(z, 0.f);
            float f = CONST_C * zz;
            float sp = fmaxf(f, 0.f) + __logf(1.f + __expf(-fabsf(f)));
            if (isS) pos += sp; else nav += sp;
        }
        float4 r2 = blockReduce4(make_float4(pos, nav, 0.f, 0.f), fsh4);
        rowres = r2.x / (float)max(ns, 1) + r2.y / (float)max(nd, 1);
    }

    if (tid == 0) {
        g_rowout[i] = make_float2(valid ? rowres : 0.f, valid ? 1.f : 0.f);
        __threadfence();
        unsigned old = atomicAdd(&g_ctr, 1u);
        lastFlag = (old == NPTS - 1) ? 1 : 0;
    }
    __syncthreads();

    if (lastFlag) {
        __threadfence();
        float t = 0.f, c = 0.f;
        for (int idx = tid; idx < NPTS; idx += RT) {
            float2 rv = g_rowout[idx];
            t += rv.x; c += rv.y;
        }
        float4 r3 = blockReduce4(make_float4(t, c, 0.f, 0.f), fsh4);
        if (tid == 0) out[0] = (r3.y > 0.f) ? r3.x / fmaxf(r3.y, 1.f) : 0.f;
    }
}

// ---------------- launch ----------------
extern "C" void kernel_launch(void* const* d_in, const int* in_sizes, int n_in,
                              void* d_out, int out_size) {
    const float* u = (const float*)d_in[0];
    const float* v = (const float*)d_in[1];
    const int*   y = (const int*)d_in[2];

    cudaFuncSetAttribute(gemm_kernel, cudaFuncAttributeMaxDynamicSharedMemorySize, GSMEM);

    prep_kernel<<<(NPTS * KW) / 256, 256>>>(u, v, y);
    dim3 gg(NPTS / 128, NPTS / 128);
    gemm_kernel<<<gg, 256, GSMEM>>>();
    row_kernel<<<NPTS, RT>>>((float*)d_out);
}